// round 1
// baseline (speedup 1.0000x reference)
#include <cuda_runtime.h>
#include <math.h>

// ---------------- problem constants ----------------
#define B_SZ   8
#define N_SEQ  4096
#define DIMC   512
#define HEADS  8
#define DHEAD  64
#define M_LM   256
#define L_LM   16          // N_SEQ / M_LM
#define BH     64          // B_SZ * HEADS
#define ROWS   32768       // B_SZ * N_SEQ
#define INNER3 1536
#define SCALE_Q 0.125f     // 64^-0.5
#define LN_EPS 1e-5f

// ---------------- device scratch ----------------
__device__ float g_nrm[ROWS * DIMC];            // 64 MB
__device__ float g_q[BH * N_SEQ * DHEAD];       // 64 MB
__device__ float g_k[BH * N_SEQ * DHEAD];       // 64 MB
__device__ float g_v[BH * N_SEQ * DHEAD];       // 64 MB
__device__ float g_ql[BH * L_LM * DHEAD];
__device__ float g_kl[BH * L_LM * DHEAD];
__device__ float g_attn1[BH * N_SEQ * L_LM];    // 16 MB
__device__ float g_sim3[BH * L_LM * N_SEQ];     // 16 MB
__device__ float g_t1[BH * L_LM * DHEAD];
__device__ float g_t2[BH * L_LM * DHEAD];
__device__ float g_attn_out[ROWS * DIMC];       // 64 MB

// ---------------- K1: LayerNorm ----------------
// grid 4096, block (32,8): one warp per row of 512
__global__ void k_layernorm(const float* __restrict__ x,
                            const float* __restrict__ gamma,
                            const float* __restrict__ beta) {
    int row = blockIdx.x * 8 + threadIdx.y;
    const float4* xr = (const float4*)(x + (size_t)row * DIMC);
    float4 v[4];
    float s = 0.f, ss = 0.f;
#pragma unroll
    for (int i = 0; i < 4; i++) {
        v[i] = xr[threadIdx.x + 32 * i];
        s  += v[i].x + v[i].y + v[i].z + v[i].w;
        ss += v[i].x * v[i].x + v[i].y * v[i].y + v[i].z * v[i].z + v[i].w * v[i].w;
    }
#pragma unroll
    for (int o = 16; o > 0; o >>= 1) {
        s  += __shfl_xor_sync(0xffffffffu, s, o);
        ss += __shfl_xor_sync(0xffffffffu, ss, o);
    }
    float mean = s * (1.f / DIMC);
    float var  = ss * (1.f / DIMC) - mean * mean;
    float rstd = rsqrtf(var + LN_EPS);
    float4* yr = (float4*)(g_nrm + (size_t)row * DIMC);
    const float4* gr = (const float4*)gamma;
    const float4* br = (const float4*)beta;
#pragma unroll
    for (int i = 0; i < 4; i++) {
        int c = threadIdx.x + 32 * i;
        float4 g4 = gr[c], b4 = br[c], o4;
        o4.x = (v[i].x - mean) * rstd * g4.x + b4.x;
        o4.y = (v[i].y - mean) * rstd * g4.y + b4.y;
        o4.z = (v[i].z - mean) * rstd * g4.z + b4.z;
        o4.w = (v[i].w - mean) * rstd * g4.w + b4.w;
        yr[c] = o4;
    }
}

// ---------------- SGEMM core (128x128x16, 8x8/thread) ----------------
// K2: qkv = nrm @ w_qkv, scattered into q/k/v (b,h,n,d) with q scaled
__global__ __launch_bounds__(256, 1) void k_gemm_qkv(const float* __restrict__ Bw) {
    __shared__ float As[16][128];
    __shared__ float Bs[16][128];
    const int tid = threadIdx.x;
    const int bm = blockIdx.y * 128;
    const int bn = blockIdx.x * 128;
    const int tr = (tid / 16) * 8;
    const int tc = (tid % 16) * 8;
    float acc[8][8];
#pragma unroll
    for (int i = 0; i < 8; i++)
#pragma unroll
        for (int j = 0; j < 8; j++) acc[i][j] = 0.f;

    for (int k0 = 0; k0 < DIMC; k0 += 16) {
#pragma unroll
        for (int t = 0; t < 2; t++) {
            int idx = tid + t * 256;
            int ar = idx >> 2, ac = (idx & 3) << 2;
            float4 av = *(const float4*)&g_nrm[(size_t)(bm + ar) * DIMC + k0 + ac];
            As[ac + 0][ar] = av.x; As[ac + 1][ar] = av.y;
            As[ac + 2][ar] = av.z; As[ac + 3][ar] = av.w;
            int br = idx >> 5, bc = (idx & 31) << 2;
            *(float4*)&Bs[br][bc] = *(const float4*)&Bw[(size_t)(k0 + br) * INNER3 + bn + bc];
        }
        __syncthreads();
#pragma unroll
        for (int kk = 0; kk < 16; kk++) {
            float4 a0 = *(const float4*)&As[kk][tr];
            float4 a1 = *(const float4*)&As[kk][tr + 4];
            float4 b0 = *(const float4*)&Bs[kk][tc];
            float4 b1 = *(const float4*)&Bs[kk][tc + 4];
            float a[8] = {a0.x, a0.y, a0.z, a0.w, a1.x, a1.y, a1.z, a1.w};
            float b[8] = {b0.x, b0.y, b0.z, b0.w, b1.x, b1.y, b1.z, b1.w};
#pragma unroll
            for (int i = 0; i < 8; i++)
#pragma unroll
                for (int j = 0; j < 8; j++) acc[i][j] += a[i] * b[j];
        }
        __syncthreads();
    }
    // scatter epilogue into (b,h,n,d)
#pragma unroll
    for (int i = 0; i < 8; i++) {
        int r = bm + tr + i;
        int bidx = r >> 12, nidx = r & 4095;
#pragma unroll
        for (int j = 0; j < 8; j += 4) {
            int c = bn + tc + j;
            int which = c >> 9;
            int within = c & 511;
            int hh = within >> 6, dd = within & 63;
            float* dst = (which == 0) ? g_q : (which == 1) ? g_k : g_v;
            float sc = (which == 0) ? SCALE_Q : 1.f;
            size_t off = ((size_t)(bidx * HEADS + hh) * N_SEQ + nidx) * DHEAD + dd;
            float4 val = make_float4(acc[i][j] * sc, acc[i][j + 1] * sc,
                                     acc[i][j + 2] * sc, acc[i][j + 3] * sc);
            *(float4*)&dst[off] = val;
        }
    }
}

// K9: out = attn_out @ w_out + b_out + x
__global__ __launch_bounds__(256, 1) void k_gemm_out(const float* __restrict__ Bw,
                                                     const float* __restrict__ x,
                                                     const float* __restrict__ bias,
                                                     float* __restrict__ out) {
    __shared__ float As[16][128];
    __shared__ float Bs[16][128];
    const int tid = threadIdx.x;
    const int bm = blockIdx.y * 128;
    const int bn = blockIdx.x * 128;
    const int tr = (tid / 16) * 8;
    const int tc = (tid % 16) * 8;
    float acc[8][8];
#pragma unroll
    for (int i = 0; i < 8; i++)
#pragma unroll
        for (int j = 0; j < 8; j++) acc[i][j] = 0.f;

    for (int k0 = 0; k0 < DIMC; k0 += 16) {
#pragma unroll
        for (int t = 0; t < 2; t++) {
            int idx = tid + t * 256;
            int ar = idx >> 2, ac = (idx & 3) << 2;
            float4 av = *(const float4*)&g_attn_out[(size_t)(bm + ar) * DIMC + k0 + ac];
            As[ac + 0][ar] = av.x; As[ac + 1][ar] = av.y;
            As[ac + 2][ar] = av.z; As[ac + 3][ar] = av.w;
            int br = idx >> 5, bc = (idx & 31) << 2;
            *(float4*)&Bs[br][bc] = *(const float4*)&Bw[(size_t)(k0 + br) * DIMC + bn + bc];
        }
        __syncthreads();
#pragma unroll
        for (int kk = 0; kk < 16; kk++) {
            float4 a0 = *(const float4*)&As[kk][tr];
            float4 a1 = *(const float4*)&As[kk][tr + 4];
            float4 b0 = *(const float4*)&Bs[kk][tc];
            float4 b1 = *(const float4*)&Bs[kk][tc + 4];
            float a[8] = {a0.x, a0.y, a0.z, a0.w, a1.x, a1.y, a1.z, a1.w};
            float b[8] = {b0.x, b0.y, b0.z, b0.w, b1.x, b1.y, b1.z, b1.w};
#pragma unroll
            for (int i = 0; i < 8; i++)
#pragma unroll
                for (int j = 0; j < 8; j++) acc[i][j] += a[i] * b[j];
        }
        __syncthreads();
    }
#pragma unroll
    for (int i = 0; i < 8; i++) {
        size_t rb = (size_t)(bm + tr + i) * DIMC;
#pragma unroll
        for (int j = 0; j < 8; j += 4) {
            int c = bn + tc + j;
            float4 xv = *(const float4*)&x[rb + c];
            float4 bv = *(const float4*)&bias[c];
            float4 o4 = make_float4(acc[i][j] + xv.x + bv.x,
                                    acc[i][j + 1] + xv.y + bv.y,
                                    acc[i][j + 2] + xv.z + bv.z,
                                    acc[i][j + 3] + xv.w + bv.w);
            *(float4*)&out[rb + c] = o4;
        }
    }
}

// ---------------- K3: landmark means ----------------
// grid 2048 (first 1024: q, next 1024: k), 256 threads
__global__ void k_landmarks() {
    int id = blockIdx.x;
    int which = id >> 10;
    int bhl = id & 1023;
    int bh = bhl >> 4, l = bhl & 15;
    const float* src = which ? g_k : g_q;
    float* dst = which ? g_kl : g_ql;
    int d = threadIdx.x & 63, part = threadIdx.x >> 6;
    const float* base = src + ((size_t)bh * N_SEQ + l * M_LM + part * 64) * DHEAD + d;
    float s = 0.f;
#pragma unroll 8
    for (int j = 0; j < 64; j++) s += base[(size_t)j * DHEAD];
    __shared__ float red[4][64];
    red[part][d] = s;
    __syncthreads();
    if (part == 0)
        dst[(bh * L_LM + l) * DHEAD + d] =
            (red[0][d] + red[1][d] + red[2][d] + red[3][d]) * (1.f / M_LM);
}

// ---------------- K4: attn1 = softmax(q @ k_l^T) ----------------
// grid (64, 16), 256 threads; one thread per query row
__global__ void k_sim1() {
    int bh = blockIdx.x;
    int row = blockIdx.y * 256 + threadIdx.x;
    __shared__ float kls[L_LM][DHEAD];
    for (int i = threadIdx.x; i < L_LM * DHEAD; i += 256)
        kls[i >> 6][i & 63] = g_kl[bh * L_LM * DHEAD + i];
    __syncthreads();
    const float* qrow = &g_q[((size_t)bh * N_SEQ + row) * DHEAD];
    float s[L_LM];
#pragma unroll
    for (int l = 0; l < L_LM; l++) s[l] = 0.f;
    for (int kk = 0; kk < DHEAD; kk += 4) {
        float4 qv = *(const float4*)&qrow[kk];
#pragma unroll
        for (int l = 0; l < L_LM; l++)
            s[l] += qv.x * kls[l][kk] + qv.y * kls[l][kk + 1] +
                    qv.z * kls[l][kk + 2] + qv.w * kls[l][kk + 3];
    }
    float mx = s[0];
#pragma unroll
    for (int l = 1; l < L_LM; l++) mx = fmaxf(mx, s[l]);
    float sum = 0.f;
#pragma unroll
    for (int l = 0; l < L_LM; l++) { s[l] = __expf(s[l] - mx); sum += s[l]; }
    float inv = 1.f / sum;
    float* dst = &g_attn1[((size_t)bh * N_SEQ + row) * L_LM];
#pragma unroll
    for (int l = 0; l < L_LM; l += 4)
        *(float4*)&dst[l] = make_float4(s[l] * inv, s[l + 1] * inv, s[l + 2] * inv, s[l + 3] * inv);
}

// ---------------- K5: sim3 = q_l @ k^T ----------------
// grid (64, 16), 256 threads; one thread per key column
__global__ void k_sim3() {
    int bh = blockIdx.x;
    int j = blockIdx.y * 256 + threadIdx.x;
    __shared__ float qls[L_LM][DHEAD];
    for (int i = threadIdx.x; i < L_LM * DHEAD; i += 256)
        qls[i >> 6][i & 63] = g_ql[bh * L_LM * DHEAD + i];
    __syncthreads();
    const float* krow = &g_k[((size_t)bh * N_SEQ + j) * DHEAD];
    float s[L_LM];
#pragma unroll
    for (int l = 0; l < L_LM; l++) s[l] = 0.f;
    for (int kk = 0; kk < DHEAD; kk += 4) {
        float4 kv = *(const float4*)&krow[kk];
#pragma unroll
        for (int l = 0; l < L_LM; l++)
            s[l] += kv.x * qls[l][kk] + kv.y * qls[l][kk + 1] +
                    kv.z * qls[l][kk + 2] + kv.w * qls[l][kk + 3];
    }
#pragma unroll
    for (int l = 0; l < L_LM; l++)
        g_sim3[((size_t)bh * L_LM + l) * N_SEQ + j] = s[l];
}

// ---------------- K6: softmax over rows of 4096 ----------------
// grid 1024, 256 threads
__global__ void k_softmax_rows() {
    __shared__ float red[8];
    float* row = g_sim3 + (size_t)blockIdx.x * N_SEQ;
    int t = threadIdx.x, lane = t & 31, warp = t >> 5;
    float v[16];
    float mx = -1e30f;
#pragma unroll
    for (int i = 0; i < 16; i++) { v[i] = row[t + 256 * i]; mx = fmaxf(mx, v[i]); }
#pragma unroll
    for (int o = 16; o > 0; o >>= 1) mx = fmaxf(mx, __shfl_xor_sync(0xffffffffu, mx, o));
    if (lane == 0) red[warp] = mx;
    __syncthreads();
    mx = red[0];
#pragma unroll
    for (int w = 1; w < 8; w++) mx = fmaxf(mx, red[w]);
    __syncthreads();
    float sum = 0.f;
#pragma unroll
    for (int i = 0; i < 16; i++) { v[i] = __expf(v[i] - mx); sum += v[i]; }
#pragma unroll
    for (int o = 16; o > 0; o >>= 1) sum += __shfl_xor_sync(0xffffffffu, sum, o);
    if (lane == 0) red[warp] = sum;
    __syncthreads();
    sum = 0.f;
#pragma unroll
    for (int w = 0; w < 8; w++) sum += red[w];
    float inv = 1.f / sum;
#pragma unroll
    for (int i = 0; i < 16; i++) row[t + 256 * i] = v[i] * inv;
}

// ---------------- K7: t1 = attn3 @ v ----------------
// grid 64, 256 threads
__global__ void k_t1() {
    int bh = blockIdx.x;
    __shared__ float a_s[L_LM][128];
    __shared__ float v_s[128][DHEAD];
    int d = threadIdx.x & 63;
    int lb = threadIdx.x >> 6;           // 0..3
    float acc[4] = {0.f, 0.f, 0.f, 0.f};
    for (int j0 = 0; j0 < N_SEQ; j0 += 128) {
        for (int i = threadIdx.x; i < L_LM * 128; i += 256) {
            int l = i >> 7, jj = i & 127;
            a_s[l][jj] = g_sim3[((size_t)bh * L_LM + l) * N_SEQ + j0 + jj];
        }
        for (int i = threadIdx.x; i < 128 * DHEAD / 4; i += 256)
            ((float4*)v_s)[i] = *(const float4*)&g_v[((size_t)bh * N_SEQ + j0) * DHEAD + i * 4];
        __syncthreads();
        for (int jj = 0; jj < 128; jj++) {
            float vv = v_s[jj][d];
#pragma unroll
            for (int p = 0; p < 4; p++) acc[p] += a_s[lb + 4 * p][jj] * vv;
        }
        __syncthreads();
    }
#pragma unroll
    for (int p = 0; p < 4; p++)
        g_t1[((size_t)bh * L_LM + lb + 4 * p) * DHEAD + d] = acc[p];
}

// ---------------- K8: sim2 + softmax + Moore-Penrose pinv + t2 ----------------
// grid 64, 256 threads (exactly 16x16)
#define MM16(Cm, Am, Bm)                                        \
    {                                                           \
        float r_ = 0.f;                                         \
        _Pragma("unroll") for (int kk_ = 0; kk_ < 16; kk_++)    \
            r_ += Am[i][kk_] * Bm[kk_][j];                      \
        __syncthreads();                                        \
        Cm[i][j] = r_;                                          \
        __syncthreads();                                        \
    }

__global__ void k_pinv() {
    int bh = blockIdx.x;
    int tid = threadIdx.x;
    int i = tid >> 4, j = tid & 15;
    __shared__ float X[16][16], Z[16][16], XZ[16][16], T[16][16], U[16][16];
    __shared__ float t1s[16][64];
    __shared__ float sden;
    // sim2[i][j]
    {
        const float* qi = &g_ql[(bh * L_LM + i) * DHEAD];
        const float* kj = &g_kl[(bh * L_LM + j) * DHEAD];
        float s = 0.f;
#pragma unroll
        for (int kk = 0; kk < DHEAD; kk++) s += qi[kk] * kj[kk];
        X[i][j] = s;
    }
    __syncthreads();
    // row softmax (16 threads serial over their row)
    if (tid < 16) {
        float mx = -1e30f;
#pragma unroll
        for (int c = 0; c < 16; c++) mx = fmaxf(mx, X[tid][c]);
        float sm = 0.f;
#pragma unroll
        for (int c = 0; c < 16; c++) { float e = __expf(X[tid][c] - mx); X[tid][c] = e; sm += e; }
        float inv = 1.f / sm;
#pragma unroll
        for (int c = 0; c < 16; c++) X[tid][c] *= inv;
    }
    __syncthreads();
    if (tid == 0) {
        float mc = 0.f, mr = 0.f;
        for (int r = 0; r < 16; r++) {
            float s = 0.f;
            for (int c = 0; c < 16; c++) s += fabsf(X[r][c]);
            mc = fmaxf(mc, s);
        }
        for (int c = 0; c < 16; c++) {
            float s = 0.f;
            for (int r = 0; r < 16; r++) s += fabsf(X[r][c]);
            mr = fmaxf(mr, s);
        }
        float den = mc * mr;
        sden = (den == 0.f) ? 1e-8f : den;
    }
    __syncthreads();
    Z[i][j] = X[j][i] / sden;
    __syncthreads();
    for (int it = 0; it < 6; it++) {
        MM16(XZ, X, Z);
        T[i][j] = (i == j ? 7.f : 0.f) - XZ[i][j];
        __syncthreads();
        MM16(U, XZ, T);
        T[i][j] = (i == j ? 15.f : 0.f) - U[i][j];
        __syncthreads();
        MM16(U, XZ, T);
        T[i][j] = (i == j ? 13.f : 0.f) - U[i][j];
        __syncthreads();
        MM16(U, Z, T);
        Z[i][j] = 0.25f * U[i][j];
        __syncthreads();
    }
    // t2 = Z @ t1
    for (int p = tid; p < L_LM * DHEAD; p += 256)
        ((float*)t1s)[p] = g_t1[(size_t)bh * L_LM * DHEAD + p];
    __syncthreads();
#pragma unroll
    for (int p = 0; p < 4; p++) {
        int idx = tid + 256 * p;
        int l = idx >> 6, d = idx & 63;
        float r = 0.f;
#pragma unroll
        for (int kk = 0; kk < 16; kk++) r += Z[l][kk] * t1s[kk][d];
        g_t2[(size_t)bh * L_LM * DHEAD + idx] = r;
    }
}

// ---------------- K9: attn_out = rearrange(attn1 @ t2 + v) ----------------
// grid (64, 1024), 256 threads; 4 rows per block
__global__ void k_attnout() {
    int bh = blockIdx.x;
    int bidx = bh >> 3, h = bh & 7;
    int row = blockIdx.y * 4 + (threadIdx.x >> 6);
    int d = threadIdx.x & 63;
    __shared__ float t2s[L_LM][DHEAD];
    for (int i = threadIdx.x; i < L_LM * DHEAD; i += 256)
        ((float*)t2s)[i] = g_t2[(size_t)bh * L_LM * DHEAD + i];
    __syncthreads();
    const float* a1 = &g_attn1[((size_t)bh * N_SEQ + row) * L_LM];
    float acc = g_v[((size_t)bh * N_SEQ + row) * DHEAD + d];
#pragma unroll
    for (int l = 0; l < L_LM; l++) acc += a1[l] * t2s[l][d];
    g_attn_out[((size_t)bidx * N_SEQ + row) * DIMC + h * DHEAD + d] = acc;
}

// ---------------- launch ----------------
extern "C" void kernel_launch(void* const* d_in, const int* in_sizes, int n_in,
                              void* d_out, int out_size) {
    const float* x     = (const float*)d_in[0];
    const float* ln_g  = (const float*)d_in[1];
    const float* ln_b  = (const float*)d_in[2];
    const float* w_qkv = (const float*)d_in[3];
    const float* w_out = (const float*)d_in[4];
    const float* b_out = (const float*)d_in[5];
    float* out = (float*)d_out;

    k_layernorm<<<ROWS / 8, dim3(32, 8)>>>(x, ln_g, ln_b);
    k_gemm_qkv<<<dim3(INNER3 / 128, ROWS / 128), 256>>>(w_qkv);
    k_landmarks<<<2048, 256>>>();
    k_sim1<<<dim3(BH, N_SEQ / 256), 256>>>();
    k_sim3<<<dim3(BH, N_SEQ / 256), 256>>>();
    k_softmax_rows<<<BH * L_LM, 256>>>();
    k_t1<<<BH, 256>>>();
    k_pinv<<<BH, 256>>>();
    k_attnout<<<dim3(BH, N_SEQ / 4), 256>>>();
    k_gemm_out<<<dim3(DIMC / 128, ROWS / 128), 256>>>(w_out, x, b_out, out);
}

// round 3
// speedup vs baseline: 1.1696x; 1.1696x over previous
#include <cuda_runtime.h>
#include <math.h>
#include <mma.h>

using namespace nvcuda;

// ---------------- problem constants ----------------
#define B_SZ   8
#define N_SEQ  4096
#define DIMC   512
#define HEADS  8
#define DHEAD  64
#define M_LM   256
#define L_LM   16          // N_SEQ / M_LM
#define BH     64          // B_SZ * HEADS
#define ROWS   32768       // B_SZ * N_SEQ
#define INNER3 1536
#define SCALE_Q 0.125f     // 64^-0.5
#define LN_EPS 1e-5f

// ---------------- device scratch ----------------
__device__ float g_nrm[ROWS * DIMC];            // 64 MB
__device__ float g_qkv[(size_t)ROWS * INNER3];  // 192 MB  (b, n, 3*inner) row-major; q pre-scaled
__device__ float g_ql[BH * L_LM * DHEAD];
__device__ float g_kl[BH * L_LM * DHEAD];
__device__ float g_attn1[BH * N_SEQ * L_LM];    // 16 MB
__device__ float g_sim3[BH * L_LM * N_SEQ];     // 16 MB
__device__ float g_t1[BH * L_LM * DHEAD];
__device__ float g_t2[BH * L_LM * DHEAD];
__device__ float g_attn_out[ROWS * DIMC];       // 64 MB

// ---------------- K1: LayerNorm ----------------
__global__ void k_layernorm(const float* __restrict__ x,
                            const float* __restrict__ gamma,
                            const float* __restrict__ beta) {
    int row = blockIdx.x * 8 + threadIdx.y;
    const float4* xr = (const float4*)(x + (size_t)row * DIMC);
    float4 v[4];
    float s = 0.f, ss = 0.f;
#pragma unroll
    for (int i = 0; i < 4; i++) {
        v[i] = xr[threadIdx.x + 32 * i];
        s  += v[i].x + v[i].y + v[i].z + v[i].w;
        ss += v[i].x * v[i].x + v[i].y * v[i].y + v[i].z * v[i].z + v[i].w * v[i].w;
    }
#pragma unroll
    for (int o = 16; o > 0; o >>= 1) {
        s  += __shfl_xor_sync(0xffffffffu, s, o);
        ss += __shfl_xor_sync(0xffffffffu, ss, o);
    }
    float mean = s * (1.f / DIMC);
    float var  = ss * (1.f / DIMC) - mean * mean;
    float rstd = rsqrtf(var + LN_EPS);
    float4* yr = (float4*)(g_nrm + (size_t)row * DIMC);
    const float4* gr = (const float4*)gamma;
    const float4* br = (const float4*)beta;
#pragma unroll
    for (int i = 0; i < 4; i++) {
        int c = threadIdx.x + 32 * i;
        float4 g4 = gr[c], b4 = br[c], o4;
        o4.x = (v[i].x - mean) * rstd * g4.x + b4.x;
        o4.y = (v[i].y - mean) * rstd * g4.y + b4.y;
        o4.z = (v[i].z - mean) * rstd * g4.z + b4.z;
        o4.w = (v[i].w - mean) * rstd * g4.w + b4.w;
        yr[c] = o4;
    }
}

// ---------------- TF32 WMMA GEMM: 128x128x32 tile, 8 warps (2x4), 64x32/warp ----
#define BM 128
#define BN 128
#define BKT 32

// K2: qkv = nrm @ w_qkv  -> g_qkv (row-major), q columns scaled by SCALE_Q
__global__ __launch_bounds__(256) void k_gemm_qkv(const float* __restrict__ Bw) {
    __shared__ float As[BM][BKT + 8];        // ld 40
    __shared__ float Bs[BKT][BN + 8];        // ld 136
    __shared__ float stage[8][16][16];
    const int tid = threadIdx.x;
    const int warp = tid >> 5, lane = tid & 31;
    const int wr = warp >> 2, wc = warp & 3;
    const int bm = blockIdx.y * BM, bn = blockIdx.x * BN;

    wmma::fragment<wmma::accumulator, 16, 16, 8, float> acc[4][2];
#pragma unroll
    for (int r = 0; r < 4; r++)
#pragma unroll
        for (int c = 0; c < 2; c++) wmma::fill_fragment(acc[r][c], 0.f);

    for (int k0 = 0; k0 < DIMC; k0 += BKT) {
#pragma unroll
        for (int t = 0; t < 4; t++) {
            int idx = tid + t * 256;
            int row = idx >> 3, c4 = idx & 7;
            *(float4*)&As[row][c4 * 4] =
                *(const float4*)&g_nrm[(size_t)(bm + row) * DIMC + k0 + c4 * 4];
            int brow = idx >> 5, bc4 = idx & 31;
            *(float4*)&Bs[brow][bc4 * 4] =
                *(const float4*)&Bw[(size_t)(k0 + brow) * INNER3 + bn + bc4 * 4];
        }
        __syncthreads();
#pragma unroll
        for (int kk = 0; kk < BKT; kk += 8) {
            wmma::fragment<wmma::matrix_a, 16, 16, 8, wmma::precision::tf32, wmma::row_major> af[4];
            wmma::fragment<wmma::matrix_b, 16, 16, 8, wmma::precision::tf32, wmma::row_major> bf[2];
#pragma unroll
            for (int r = 0; r < 4; r++) {
                wmma::load_matrix_sync(af[r], &As[wr * 64 + r * 16][kk], BKT + 8);
#pragma unroll
                for (int t = 0; t < af[r].num_elements; t++)
                    af[r].x[t] = wmma::__float_to_tf32(af[r].x[t]);
            }
#pragma unroll
            for (int c = 0; c < 2; c++) {
                wmma::load_matrix_sync(bf[c], &Bs[kk][wc * 32 + c * 16], BN + 8);
#pragma unroll
                for (int t = 0; t < bf[c].num_elements; t++)
                    bf[c].x[t] = wmma::__float_to_tf32(bf[c].x[t]);
            }
#pragma unroll
            for (int r = 0; r < 4; r++)
#pragma unroll
                for (int c = 0; c < 2; c++)
                    wmma::mma_sync(acc[r][c], af[r], bf[c], acc[r][c]);
        }
        __syncthreads();
    }
    // epilogue: stage 16x16, coalesced float4 store; scale q columns
#pragma unroll
    for (int r = 0; r < 4; r++)
#pragma unroll
        for (int c = 0; c < 2; c++) {
            int row0 = bm + wr * 64 + r * 16;
            int col0 = bn + wc * 32 + c * 16;
            float sc = (col0 < 512) ? SCALE_Q : 1.f;
            wmma::store_matrix_sync(&stage[warp][0][0], acc[r][c], 16, wmma::mem_row_major);
            __syncwarp();
            int rr = lane >> 1, cc = (lane & 1) * 8;
            float4 v0 = *(float4*)&stage[warp][rr][cc];
            float4 v1 = *(float4*)&stage[warp][rr][cc + 4];
            v0.x *= sc; v0.y *= sc; v0.z *= sc; v0.w *= sc;
            v1.x *= sc; v1.y *= sc; v1.z *= sc; v1.w *= sc;
            size_t gb = (size_t)(row0 + rr) * INNER3 + col0 + cc;
            *(float4*)&g_qkv[gb] = v0;
            *(float4*)&g_qkv[gb + 4] = v1;
            __syncwarp();
        }
}

// K10: out = attn_out @ w_out + b_out + x
__global__ __launch_bounds__(256) void k_gemm_out(const float* __restrict__ Bw,
                                                  const float* __restrict__ x,
                                                  const float* __restrict__ bias,
                                                  float* __restrict__ out) {
    __shared__ float As[BM][BKT + 8];
    __shared__ float Bs[BKT][BN + 8];
    __shared__ float stage[8][16][16];
    const int tid = threadIdx.x;
    const int warp = tid >> 5, lane = tid & 31;
    const int wr = warp >> 2, wc = warp & 3;
    const int bm = blockIdx.y * BM, bn = blockIdx.x * BN;

    wmma::fragment<wmma::accumulator, 16, 16, 8, float> acc[4][2];
#pragma unroll
    for (int r = 0; r < 4; r++)
#pragma unroll
        for (int c = 0; c < 2; c++) wmma::fill_fragment(acc[r][c], 0.f);

    for (int k0 = 0; k0 < DIMC; k0 += BKT) {
#pragma unroll
        for (int t = 0; t < 4; t++) {
            int idx = tid + t * 256;
            int row = idx >> 3, c4 = idx & 7;
            *(float4*)&As[row][c4 * 4] =
                *(const float4*)&g_attn_out[(size_t)(bm + row) * DIMC + k0 + c4 * 4];
            int brow = idx >> 5, bc4 = idx & 31;
            *(float4*)&Bs[brow][bc4 * 4] =
                *(const float4*)&Bw[(size_t)(k0 + brow) * DIMC + bn + bc4 * 4];
        }
        __syncthreads();
#pragma unroll
        for (int kk = 0; kk < BKT; kk += 8) {
            wmma::fragment<wmma::matrix_a, 16, 16, 8, wmma::precision::tf32, wmma::row_major> af[4];
            wmma::fragment<wmma::matrix_b, 16, 16, 8, wmma::precision::tf32, wmma::row_major> bf[2];
#pragma unroll
            for (int r = 0; r < 4; r++) {
                wmma::load_matrix_sync(af[r], &As[wr * 64 + r * 16][kk], BKT + 8);
#pragma unroll
                for (int t = 0; t < af[r].num_elements; t++)
                    af[r].x[t] = wmma::__float_to_tf32(af[r].x[t]);
            }
#pragma unroll
            for (int c = 0; c < 2; c++) {
                wmma::load_matrix_sync(bf[c], &Bs[kk][wc * 32 + c * 16], BN + 8);
#pragma unroll
                for (int t = 0; t < bf[c].num_elements; t++)
                    bf[c].x[t] = wmma::__float_to_tf32(bf[c].x[t]);
            }
#pragma unroll
            for (int r = 0; r < 4; r++)
#pragma unroll
                for (int c = 0; c < 2; c++)
                    wmma::mma_sync(acc[r][c], af[r], bf[c], acc[r][c]);
        }
        __syncthreads();
    }
#pragma unroll
    for (int r = 0; r < 4; r++)
#pragma unroll
        for (int c = 0; c < 2; c++) {
            int row0 = bm + wr * 64 + r * 16;
            int col0 = bn + wc * 32 + c * 16;
            wmma::store_matrix_sync(&stage[warp][0][0], acc[r][c], 16, wmma::mem_row_major);
            __syncwarp();
            int rr = lane >> 1, cc = (lane & 1) * 8;
            float4 v0 = *(float4*)&stage[warp][rr][cc];
            float4 v1 = *(float4*)&stage[warp][rr][cc + 4];
            size_t gb = (size_t)(row0 + rr) * DIMC + col0 + cc;
            float4 x0 = *(const float4*)&x[gb];
            float4 x1 = *(const float4*)&x[gb + 4];
            float4 b0 = *(const float4*)&bias[col0 + cc];
            float4 b1 = *(const float4*)&bias[col0 + cc + 4];
            v0.x += x0.x + b0.x; v0.y += x0.y + b0.y;
            v0.z += x0.z + b0.z; v0.w += x0.w + b0.w;
            v1.x += x1.x + b1.x; v1.y += x1.y + b1.y;
            v1.z += x1.z + b1.z; v1.w += x1.w + b1.w;
            *(float4*)&out[gb] = v0;
            *(float4*)&out[gb + 4] = v1;
            __syncwarp();
        }
}

// ---------------- K3: landmark means ----------------
// grid 2048 (first 1024: q, next 1024: k), 256 threads
__global__ void k_landmarks() {
    int id = blockIdx.x;
    int which = id >> 10;                 // 0 = q, 1 = k
    int bhl = id & 1023;
    int bh = bhl >> 4, l = bhl & 15;
    int b = bh >> 3, h = bh & 7;
    float* dst = which ? g_kl : g_ql;
    int d = threadIdx.x & 63, part = threadIdx.x >> 6;
    size_t base = ((size_t)(b * N_SEQ + l * M_LM + part * 64)) * INNER3 +
                  which * DIMC + h * DHEAD + d;
    float s = 0.f;
#pragma unroll 8
    for (int j = 0; j < 64; j++) s += g_qkv[base + (size_t)j * INNER3];
    __shared__ float red[4][64];
    red[part][d] = s;
    __syncthreads();
    if (part == 0)
        dst[(bh * L_LM + l) * DHEAD + d] =
            (red[0][d] + red[1][d] + red[2][d] + red[3][d]) * (1.f / M_LM);
}

// ---------------- K4: attn1 = softmax(q @ k_l^T) ----------------
__global__ void k_sim1() {
    int bh = blockIdx.x;
    int b = bh >> 3, h = bh & 7;
    int row = blockIdx.y * 256 + threadIdx.x;
    __shared__ float kls[L_LM][DHEAD];
    for (int i = threadIdx.x; i < L_LM * DHEAD; i += 256)
        kls[i >> 6][i & 63] = g_kl[bh * L_LM * DHEAD + i];
    __syncthreads();
    const float* qrow = &g_qkv[((size_t)(b * N_SEQ + row)) * INNER3 + h * DHEAD];
    float s[L_LM];
#pragma unroll
    for (int l = 0; l < L_LM; l++) s[l] = 0.f;
    for (int kk = 0; kk < DHEAD; kk += 4) {
        float4 qv = *(const float4*)&qrow[kk];
#pragma unroll
        for (int l = 0; l < L_LM; l++)
            s[l] += qv.x * kls[l][kk] + qv.y * kls[l][kk + 1] +
                    qv.z * kls[l][kk + 2] + qv.w * kls[l][kk + 3];
    }
    float mx = s[0];
#pragma unroll
    for (int l = 1; l < L_LM; l++) mx = fmaxf(mx, s[l]);
    float sum = 0.f;
#pragma unroll
    for (int l = 0; l < L_LM; l++) { s[l] = __expf(s[l] - mx); sum += s[l]; }
    float inv = 1.f / sum;
    float* dst = &g_attn1[((size_t)bh * N_SEQ + row) * L_LM];
#pragma unroll
    for (int l = 0; l < L_LM; l += 4)
        *(float4*)&dst[l] = make_float4(s[l] * inv, s[l + 1] * inv, s[l + 2] * inv, s[l + 3] * inv);
}

// ---------------- K5: sim3 = q_l @ k^T ----------------
__global__ void k_sim3() {
    int bh = blockIdx.x;
    int b = bh >> 3, h = bh & 7;
    int j = blockIdx.y * 256 + threadIdx.x;
    __shared__ float qls[L_LM][DHEAD];
    for (int i = threadIdx.x; i < L_LM * DHEAD; i += 256)
        qls[i >> 6][i & 63] = g_ql[bh * L_LM * DHEAD + i];
    __syncthreads();
    const float* krow = &g_qkv[((size_t)(b * N_SEQ + j)) * INNER3 + DIMC + h * DHEAD];
    float s[L_LM];
#pragma unroll
    for (int l = 0; l < L_LM; l++) s[l] = 0.f;
    for (int kk = 0; kk < DHEAD; kk += 4) {
        float4 kv = *(const float4*)&krow[kk];
#pragma unroll
        for (int l = 0; l < L_LM; l++)
            s[l] += kv.x * qls[l][kk] + kv.y * qls[l][kk + 1] +
                    kv.z * qls[l][kk + 2] + kv.w * qls[l][kk + 3];
    }
#pragma unroll
    for (int l = 0; l < L_LM; l++)
        g_sim3[((size_t)bh * L_LM + l) * N_SEQ + j] = s[l];
}

// ---------------- K6: softmax over rows of 4096 ----------------
__global__ void k_softmax_rows() {
    __shared__ float red[8];
    float* row = g_sim3 + (size_t)blockIdx.x * N_SEQ;
    int t = threadIdx.x, lane = t & 31, warp = t >> 5;
    float v[16];
    float mx = -1e30f;
#pragma unroll
    for (int i = 0; i < 16; i++) { v[i] = row[t + 256 * i]; mx = fmaxf(mx, v[i]); }
#pragma unroll
    for (int o = 16; o > 0; o >>= 1) mx = fmaxf(mx, __shfl_xor_sync(0xffffffffu, mx, o));
    if (lane == 0) red[warp] = mx;
    __syncthreads();
    mx = red[0];
#pragma unroll
    for (int w = 1; w < 8; w++) mx = fmaxf(mx, red[w]);
    __syncthreads();
    float sum = 0.f;
#pragma unroll
    for (int i = 0; i < 16; i++) { v[i] = __expf(v[i] - mx); sum += v[i]; }
#pragma unroll
    for (int o = 16; o > 0; o >>= 1) sum += __shfl_xor_sync(0xffffffffu, sum, o);
    if (lane == 0) red[warp] = sum;
    __syncthreads();
    sum = 0.f;
#pragma unroll
    for (int w = 0; w < 8; w++) sum += red[w];
    float inv = 1.f / sum;
#pragma unroll
    for (int i = 0; i < 16; i++) row[t + 256 * i] = v[i] * inv;
}

// ---------------- K7: t1 = attn3 @ v ----------------
__global__ void k_t1() {
    int bh = blockIdx.x;
    int b = bh >> 3, h = bh & 7;
    __shared__ float a_s[L_LM][128];
    __shared__ float v_s[128][DHEAD];
    int d = threadIdx.x & 63;
    int lb = threadIdx.x >> 6;
    float acc[4] = {0.f, 0.f, 0.f, 0.f};
    for (int j0 = 0; j0 < N_SEQ; j0 += 128) {
        for (int i = threadIdx.x; i < L_LM * 128; i += 256) {
            int l = i >> 7, jj = i & 127;
            a_s[l][jj] = g_sim3[((size_t)bh * L_LM + l) * N_SEQ + j0 + jj];
        }
        for (int i = threadIdx.x; i < 128 * 16; i += 256) {
            int row = i >> 4, d4 = i & 15;
            *(float4*)&v_s[row][d4 * 4] =
                *(const float4*)&g_qkv[((size_t)(b * N_SEQ + j0 + row)) * INNER3 +
                                       2 * DIMC + h * DHEAD + d4 * 4];
        }
        __syncthreads();
        for (int jj = 0; jj < 128; jj++) {
            float vv = v_s[jj][d];
#pragma unroll
            for (int p = 0; p < 4; p++) acc[p] += a_s[lb + 4 * p][jj] * vv;
        }
        __syncthreads();
    }
#pragma unroll
    for (int p = 0; p < 4; p++)
        g_t1[((size_t)bh * L_LM + lb + 4 * p) * DHEAD + d] = acc[p];
}

// ---------------- K8: sim2 + softmax + pinv + t2 ----------------
#define MM16(Cm, Am, Bm)                                        \
    {                                                           \
        float r_ = 0.f;                                         \
        _Pragma("unroll") for (int kk_ = 0; kk_ < 16; kk_++)    \
            r_ += Am[i][kk_] * Bm[kk_][j];                      \
        __syncthreads();                                        \
        Cm[i][j] = r_;                                          \
        __syncthreads();                                        \
    }

__global__ void k_pinv() {
    int bh = blockIdx.x;
    int tid = threadIdx.x;
    int i = tid >> 4, j = tid & 15;
    __shared__ float X[16][16], Z[16][16], XZ[16][16], T[16][16], U[16][16];
    __shared__ float t1s[16][64];
    __shared__ float sden;
    {
        const float* qi = &g_ql[(bh * L_LM + i) * DHEAD];
        const float* kj = &g_kl[(bh * L_LM + j) * DHEAD];
        float s = 0.f;
#pragma unroll
        for (int kk = 0; kk < DHEAD; kk++) s += qi[kk] * kj[kk];
        X[i][j] = s;
    }
    __syncthreads();
    if (tid < 16) {
        float mx = -1e30f;
#pragma unroll
        for (int c = 0; c < 16; c++) mx = fmaxf(mx, X[tid][c]);
        float sm = 0.f;
#pragma unroll
        for (int c = 0; c < 16; c++) { float e = __expf(X[tid][c] - mx); X[tid][c] = e; sm += e; }
        float inv = 1.f / sm;
#pragma unroll
        for (int c = 0; c < 16; c++) X[tid][c] *= inv;
    }
    __syncthreads();
    if (tid == 0) {
        float mc = 0.f, mr = 0.f;
        for (int r = 0; r < 16; r++) {
            float s = 0.f;
            for (int c = 0; c < 16; c++) s += fabsf(X[r][c]);
            mc = fmaxf(mc, s);
        }
        for (int c = 0; c < 16; c++) {
            float s = 0.f;
            for (int r = 0; r < 16; r++) s += fabsf(X[r][c]);
            mr = fmaxf(mr, s);
        }
        float den = mc * mr;
        sden = (den == 0.f) ? 1e-8f : den;
    }
    __syncthreads();
    Z[i][j] = X[j][i] / sden;
    __syncthreads();
    for (int it = 0; it < 6; it++) {
        MM16(XZ, X, Z);
        T[i][j] = (i == j ? 7.f : 0.f) - XZ[i][j];
        __syncthreads();
        MM16(U, XZ, T);
        T[i][j] = (i == j ? 15.f : 0.f) - U[i][j];
        __syncthreads();
        MM16(U, XZ, T);
        T[i][j] = (i == j ? 13.f : 0.f) - U[i][j];
        __syncthreads();
        MM16(U, Z, T);
        Z[i][j] = 0.25f * U[i][j];
        __syncthreads();
    }
    for (int p = tid; p < L_LM * DHEAD; p += 256)
        ((float*)t1s)[p] = g_t1[(size_t)bh * L_LM * DHEAD + p];
    __syncthreads();
#pragma unroll
    for (int p = 0; p < 4; p++) {
        int idx = tid + 256 * p;
        int l = idx >> 6, d = idx & 63;
        float r = 0.f;
#pragma unroll
        for (int kk = 0; kk < 16; kk++) r += Z[l][kk] * t1s[kk][d];
        g_t2[(size_t)bh * L_LM * DHEAD + idx] = r;
    }
}

// ---------------- K9: attn_out = rearrange(attn1 @ t2 + v) ----------------
__global__ void k_attnout() {
    int bh = blockIdx.x;
    int b = bh >> 3, h = bh & 7;
    int row = blockIdx.y * 4 + (threadIdx.x >> 6);
    int d = threadIdx.x & 63;
    __shared__ float t2s[L_LM][DHEAD];
    for (int i = threadIdx.x; i < L_LM * DHEAD; i += 256)
        ((float*)t2s)[i] = g_t2[(size_t)bh * L_LM * DHEAD + i];
    __syncthreads();
    const float* a1 = &g_attn1[((size_t)bh * N_SEQ + row) * L_LM];
    float acc = g_qkv[((size_t)(b * N_SEQ + row)) * INNER3 + 2 * DIMC + h * DHEAD + d];
#pragma unroll
    for (int l = 0; l < L_LM; l++) acc += a1[l] * t2s[l][d];
    g_attn_out[((size_t)b * N_SEQ + row) * DIMC + h * DHEAD + d] = acc;
}

// ---------------- launch ----------------
extern "C" void kernel_launch(void* const* d_in, const int* in_sizes, int n_in,
                              void* d_out, int out_size) {
    const float* x     = (const float*)d_in[0];
    const float* ln_g  = (const float*)d_in[1];
    const float* ln_b  = (const float*)d_in[2];
    const float* w_qkv = (const float*)d_in[3];
    const float* w_out = (const float*)d_in[4];
    const float* b_out = (const float*)d_in[5];
    float* out = (float*)d_out;

    k_layernorm<<<ROWS / 8, dim3(32, 8)>>>(x, ln_g, ln_b);
    k_gemm_qkv<<<dim3(INNER3 / BN, ROWS / BM), 256>>>(w_qkv);
    k_landmarks<<<2048, 256>>>();
    k_sim1<<<dim3(BH, N_SEQ / 256), 256>>>();
    k_sim3<<<dim3(BH, N_SEQ / 256), 256>>>();
    k_softmax_rows<<<BH * L_LM, 256>>>();
    k_t1<<<BH, 256>>>();
    k_pinv<<<BH, 256>>>();
    k_attnout<<<dim3(BH, N_SEQ / 4), 256>>>();
    k_gemm_out<<<dim3(DIMC / BN, ROWS / BM), 256>>>(w_out, x, b_out, out);
}

// round 7
// speedup vs baseline: 2.2334x; 1.9096x over previous
#include <cuda_runtime.h>
#include <math.h>
#include <mma.h>
#include <cstdint>

// ---------------- problem constants ----------------
#define B_SZ   8
#define N_SEQ  4096
#define DIMC   512
#define HEADS  8
#define DHEAD  64
#define M_LM   256
#define L_LM   16
#define BH     64
#define ROWS   32768
#define INNER3 1536
#define SCALE_Q 0.125f
#define LN_EPS 1e-5f

// ---------------- device scratch ----------------
__device__ float g_nrm[(size_t)ROWS * DIMC];          // 64 MB (tf32-rounded)
__device__ float g_qkv[(size_t)ROWS * INNER3];        // 192 MB
__device__ float g_attn_out[(size_t)ROWS * DIMC];     // 64 MB (tf32-rounded)
__device__ float g_wq32[DIMC * INNER3];               // 3 MB tf32-rounded w_qkv
__device__ float g_wo32[DIMC * DIMC];                 // 1 MB tf32-rounded w_out
__device__ float g_ql[BH * L_LM * DHEAD];
__device__ float g_kl[BH * L_LM * DHEAD];
__device__ float g_attn1[(size_t)BH * N_SEQ * L_LM];  // 16 MB
__device__ float g_sim3[(size_t)BH * L_LM * N_SEQ];   // 16 MB
__device__ float g_t1[BH * L_LM * DHEAD];
__device__ float g_t2[BH * L_LM * DHEAD];

// ---------------- helpers ----------------
__device__ __forceinline__ uint32_t smem_u32(const void* p) {
    uint32_t a;
    asm("{ .reg .u64 t; cvta.to.shared.u64 t, %1; cvt.u32.u64 %0, t; }" : "=r"(a) : "l"(p));
    return a;
}
#define CP_ASYNC16(dst, src) \
    asm volatile("cp.async.cg.shared.global [%0], [%1], 16;" :: "r"(dst), "l"(src))
#define CP_COMMIT() asm volatile("cp.async.commit_group;" ::: "memory")
#define CP_WAIT(n)  asm volatile("cp.async.wait_group %0;" :: "n"(n) : "memory")

#define MMA_TF32(c, a, b)                                                       \
    asm volatile("mma.sync.aligned.m16n8k8.row.col.f32.tf32.tf32.f32 "          \
        "{%0,%1,%2,%3}, {%4,%5,%6,%7}, {%8,%9}, {%0,%1,%2,%3};"                 \
        : "+f"((c)[0]), "+f"((c)[1]), "+f"((c)[2]), "+f"((c)[3])                \
        : "r"((a)[0]), "r"((a)[1]), "r"((a)[2]), "r"((a)[3]),                   \
          "r"((b)[0]), "r"((b)[1]))

__device__ __forceinline__ float to_tf32(float v) {
    uint32_t r;
    asm("cvt.rna.tf32.f32 %0, %1;" : "=r"(r) : "f"(v));
    return __uint_as_float(r);
}

// ---------------- K0: tf32-round weights ----------------
__global__ void k_prep_tf32(const float* __restrict__ src, float* __restrict__ dst) {
    int i = blockIdx.x * 256 + threadIdx.x;
    dst[i] = to_tf32(src[i]);
}

// ---------------- K1: LayerNorm -> tf32-rounded fp32 ----------------
__global__ void k_layernorm(const float* __restrict__ x,
                            const float* __restrict__ gamma,
                            const float* __restrict__ beta) {
    int row = blockIdx.x * 8 + threadIdx.y;
    const float4* xr = (const float4*)(x + (size_t)row * DIMC);
    float4 v[4];
    float s = 0.f, ss = 0.f;
#pragma unroll
    for (int i = 0; i < 4; i++) {
        v[i] = xr[threadIdx.x + 32 * i];
        s  += v[i].x + v[i].y + v[i].z + v[i].w;
        ss += v[i].x * v[i].x + v[i].y * v[i].y + v[i].z * v[i].z + v[i].w * v[i].w;
    }
#pragma unroll
    for (int o = 16; o > 0; o >>= 1) {
        s  += __shfl_xor_sync(0xffffffffu, s, o);
        ss += __shfl_xor_sync(0xffffffffu, ss, o);
    }
    float mean = s * (1.f / DIMC);
    float var  = ss * (1.f / DIMC) - mean * mean;
    float rstd = rsqrtf(var + LN_EPS);
    float4* yr = (float4*)(g_nrm + (size_t)row * DIMC);
    const float4* gr = (const float4*)gamma;
    const float4* br = (const float4*)beta;
#pragma unroll
    for (int i = 0; i < 4; i++) {
        int c = threadIdx.x + 32 * i;
        float4 g4 = gr[c], b4 = br[c], o4;
        o4.x = to_tf32((v[i].x - mean) * rstd * g4.x + b4.x);
        o4.y = to_tf32((v[i].y - mean) * rstd * g4.y + b4.y);
        o4.z = to_tf32((v[i].z - mean) * rstd * g4.z + b4.z);
        o4.w = to_tf32((v[i].w - mean) * rstd * g4.w + b4.w);
        yr[c] = o4;
    }
}

// ---------------- mma.sync TF32 GEMM ----------------
// C[ROWS][NTOT] = A[ROWS][512] @ B[512][NTOT]; tile 128x128, BK=32, 3-stage cp.async.
#define NCHUNK 16
#define A_LD 36
#define B_LD 132
#define A_ST (128 * A_LD)        // floats per A stage
#define B_ST (32 * B_LD)         // floats per B stage
#define GEMM_SMEM ((3 * (A_ST + B_ST)) * 4)

template <int NTOT, bool IS_OUT>
__global__ __launch_bounds__(256) void k_gemm_mma(
    const float* __restrict__ A, const float* __restrict__ Bw,
    const float* __restrict__ xres, const float* __restrict__ bias,
    float* __restrict__ C) {
    extern __shared__ float sm[];
    float* AsBase = sm;
    float* BsBase = sm + 3 * A_ST;
    const int tid = threadIdx.x;
    const int warp = tid >> 5, lane = tid & 31;
    const int wm = warp >> 2, wn = warp & 3;
    const int bm = blockIdx.y * 128, bn = blockIdx.x * 128;
    const int g = lane >> 2, q = lane & 3;

    float acc[4][4][4];
#pragma unroll
    for (int mt = 0; mt < 4; mt++)
#pragma unroll
        for (int nt = 0; nt < 4; nt++)
#pragma unroll
            for (int e = 0; e < 4; e++) acc[mt][nt][e] = 0.f;

    auto load_chunk = [&](int c) {
        int st = c % 3;
        float* as = AsBase + st * A_ST;
        float* bs = BsBase + st * B_ST;
        int k0 = c * 32;
#pragma unroll
        for (int t = 0; t < 4; t++) {
            int idx = tid + t * 256;
            int arow = idx >> 3, aseg = idx & 7;
            CP_ASYNC16(smem_u32(as + arow * A_LD + aseg * 4),
                       A + (size_t)(bm + arow) * DIMC + k0 + aseg * 4);
            int brow = idx >> 5, bseg = idx & 31;
            CP_ASYNC16(smem_u32(bs + brow * B_LD + bseg * 4),
                       Bw + (size_t)(k0 + brow) * NTOT + bn + bseg * 4);
        }
        CP_COMMIT();
    };

    load_chunk(0);
    load_chunk(1);

    for (int c = 0; c < NCHUNK; c++) {
        if (c == NCHUNK - 1) { CP_WAIT(0); } else { CP_WAIT(1); }
        __syncthreads();
        if (c + 2 < NCHUNK) load_chunk(c + 2);

        int st = c % 3;
        const float* as = AsBase + st * A_ST + (wm * 64 + g) * A_LD + q;
        const float* bs = BsBase + st * B_ST + q * B_LD + wn * 32 + (lane >> 2);
#pragma unroll
        for (int kk = 0; kk < 32; kk += 8) {
            uint32_t af[4][4], bf[4][2];
#pragma unroll
            for (int mt = 0; mt < 4; mt++) {
                const float* p = as + mt * 16 * A_LD + kk;
                af[mt][0] = __float_as_uint(p[0]);
                af[mt][1] = __float_as_uint(p[8 * A_LD]);
                af[mt][2] = __float_as_uint(p[4]);
                af[mt][3] = __float_as_uint(p[8 * A_LD + 4]);
            }
#pragma unroll
            for (int nt = 0; nt < 4; nt++) {
                const float* p = bs + kk * B_LD + nt * 8;
                bf[nt][0] = __float_as_uint(p[0]);
                bf[nt][1] = __float_as_uint(p[4 * B_LD]);
            }
#pragma unroll
            for (int mt = 0; mt < 4; mt++)
#pragma unroll
                for (int nt = 0; nt < 4; nt++)
                    MMA_TF32(acc[mt][nt], af[mt], bf[nt]);
        }
        __syncthreads();
    }

    // epilogue: direct register -> global float2 stores
#pragma unroll
    for (int mt = 0; mt < 4; mt++) {
        int row0 = bm + wm * 64 + mt * 16 + g;
#pragma unroll
        for (int nt = 0; nt < 4; nt++) {
            int col = bn + wn * 32 + nt * 8 + 2 * q;
            float* c = acc[mt][nt];
            if (IS_OUT) {
                size_t o0 = (size_t)row0 * NTOT + col;
                size_t o1 = (size_t)(row0 + 8) * NTOT + col;
                float2 bv = *(const float2*)&bias[col];
                float2 x0 = *(const float2*)&xres[o0];
                float2 x1 = *(const float2*)&xres[o1];
                float2 r0 = make_float2(c[0] + x0.x + bv.x, c[1] + x0.y + bv.y);
                float2 r1 = make_float2(c[2] + x1.x + bv.x, c[3] + x1.y + bv.y);
                *(float2*)&C[o0] = r0;
                *(float2*)&C[o1] = r1;
            } else {
                float sc = (col < 512) ? SCALE_Q : 1.f;
                size_t o0 = (size_t)row0 * NTOT + col;
                size_t o1 = (size_t)(row0 + 8) * NTOT + col;
                *(float2*)&C[o0] = make_float2(c[0] * sc, c[1] * sc);
                *(float2*)&C[o1] = make_float2(c[2] * sc, c[3] * sc);
            }
        }
    }
}

// ---------------- K3: landmark means ----------------
__global__ void k_landmarks() {
    int id = blockIdx.x;
    int which = id >> 10;
    int bhl = id & 1023;
    int bh = bhl >> 4, l = bhl & 15;
    int b = bh >> 3, h = bh & 7;
    float* dst = which ? g_kl : g_ql;
    int d = threadIdx.x & 63, part = threadIdx.x >> 6;
    size_t base = ((size_t)(b * N_SEQ + l * M_LM + part * 64)) * INNER3 +
                  which * DIMC + h * DHEAD + d;
    float s = 0.f;
#pragma unroll 8
    for (int j = 0; j < 64; j++) s += g_qkv[base + (size_t)j * INNER3];
    __shared__ float red[4][64];
    red[part][d] = s;
    __syncthreads();
    if (part == 0)
        dst[(bh * L_LM + l) * DHEAD + d] =
            (red[0][d] + red[1][d] + red[2][d] + red[3][d]) * (1.f / M_LM);
}

// ---------------- K4: attn1 = softmax(q @ k_l^T) ----------------
__global__ void k_sim1() {
    int bh = blockIdx.x;
    int b = bh >> 3, h = bh & 7;
    int row = blockIdx.y * 256 + threadIdx.x;
    __shared__ float kls[L_LM][DHEAD];
    for (int i = threadIdx.x; i < L_LM * DHEAD; i += 256)
        kls[i >> 6][i & 63] = g_kl[bh * L_LM * DHEAD + i];
    __syncthreads();
    const float* qrow = &g_qkv[((size_t)(b * N_SEQ + row)) * INNER3 + h * DHEAD];
    float s[L_LM];
#pragma unroll
    for (int l = 0; l < L_LM; l++) s[l] = 0.f;
    for (int kk = 0; kk < DHEAD; kk += 4) {
        float4 qv = *(const float4*)&qrow[kk];
#pragma unroll
        for (int l = 0; l < L_LM; l++)
            s[l] += qv.x * kls[l][kk] + qv.y * kls[l][kk + 1] +
                    qv.z * kls[l][kk + 2] + qv.w * kls[l][kk + 3];
    }
    float mx = s[0];
#pragma unroll
    for (int l = 1; l < L_LM; l++) mx = fmaxf(mx, s[l]);
    float sum = 0.f;
#pragma unroll
    for (int l = 0; l < L_LM; l++) { s[l] = __expf(s[l] - mx); sum += s[l]; }
    float inv = 1.f / sum;
    float* dst = &g_attn1[((size_t)bh * N_SEQ + row) * L_LM];
#pragma unroll
    for (int l = 0; l < L_LM; l += 4)
        *(float4*)&dst[l] = make_float4(s[l] * inv, s[l + 1] * inv, s[l + 2] * inv, s[l + 3] * inv);
}

// ---------------- K5: sim3 = q_l @ k^T ----------------
__global__ void k_sim3() {
    int bh = blockIdx.x;
    int b = bh >> 3, h = bh & 7;
    int j = blockIdx.y * 256 + threadIdx.x;
    __shared__ float qls[L_LM][DHEAD];
    for (int i = threadIdx.x; i < L_LM * DHEAD; i += 256)
        qls[i >> 6][i & 63] = g_ql[bh * L_LM * DHEAD + i];
    __syncthreads();
    const float* krow = &g_qkv[((size_t)(b * N_SEQ + j)) * INNER3 + DIMC + h * DHEAD];
    float s[L_LM];
#pragma unroll
    for (int l = 0; l < L_LM; l++) s[l] = 0.f;
    for (int kk = 0; kk < DHEAD; kk += 4) {
        float4 kv = *(const float4*)&krow[kk];
#pragma unroll
        for (int l = 0; l < L_LM; l++)
            s[l] += kv.x * qls[l][kk] + kv.y * qls[l][kk + 1] +
                    kv.z * qls[l][kk + 2] + kv.w * qls[l][kk + 3];
    }
#pragma unroll
    for (int l = 0; l < L_LM; l++)
        g_sim3[((size_t)bh * L_LM + l) * N_SEQ + j] = s[l];
}

// ---------------- K6: softmax over rows of 4096 ----------------
__global__ void k_softmax_rows() {
    __shared__ float red[8];
    float* row = g_sim3 + (size_t)blockIdx.x * N_SEQ;
    int t = threadIdx.x, lane = t & 31, warp = t >> 5;
    float v[16];
    float mx = -1e30f;
#pragma unroll
    for (int i = 0; i < 16; i++) { v[i] = row[t + 256 * i]; mx = fmaxf(mx, v[i]); }
#pragma unroll
    for (int o = 16; o > 0; o >>= 1) mx = fmaxf(mx, __shfl_xor_sync(0xffffffffu, mx, o));
    if (lane == 0) red[warp] = mx;
    __syncthreads();
    mx = red[0];
#pragma unroll
    for (int w = 1; w < 8; w++) mx = fmaxf(mx, red[w]);
    __syncthreads();
    float sum = 0.f;
#pragma unroll
    for (int i = 0; i < 16; i++) { v[i] = __expf(v[i] - mx); sum += v[i]; }
#pragma unroll
    for (int o = 16; o > 0; o >>= 1) sum += __shfl_xor_sync(0xffffffffu, sum, o);
    if (lane == 0) red[warp] = sum;
    __syncthreads();
    sum = 0.f;
#pragma unroll
    for (int w = 0; w < 8; w++) sum += red[w];
    float inv = 1.f / sum;
#pragma unroll
    for (int i = 0; i < 16; i++) row[t + 256 * i] = v[i] * inv;
}

// ---------------- K7: t1 = attn3 @ v ----------------
__global__ void k_t1() {
    int bh = blockIdx.x;
    int b = bh >> 3, h = bh & 7;
    __shared__ float a_s[L_LM][128];
    __shared__ float v_s[128][DHEAD];
    int d = threadIdx.x & 63;
    int lb = threadIdx.x >> 6;
    float acc[4] = {0.f, 0.f, 0.f, 0.f};
    for (int j0 = 0; j0 < N_SEQ; j0 += 128) {
        for (int i = threadIdx.x; i < L_LM * 128; i += 256) {
            int l = i >> 7, jj = i & 127;
            a_s[l][jj] = g_sim3[((size_t)bh * L_LM + l) * N_SEQ + j0 + jj];
        }
        for (int i = threadIdx.x; i < 128 * 16; i += 256) {
            int row = i >> 4, d4 = i & 15;
            *(float4*)&v_s[row][d4 * 4] =
                *(const float4*)&g_qkv[((size_t)(b * N_SEQ + j0 + row)) * INNER3 +
                                       2 * DIMC + h * DHEAD + d4 * 4];
        }
        __syncthreads();
        for (int jj = 0; jj < 128; jj++) {
            float vv = v_s[jj][d];
#pragma unroll
            for (int p = 0; p < 4; p++) acc[p] += a_s[lb + 4 * p][jj] * vv;
        }
        __syncthreads();
    }
#pragma unroll
    for (int p = 0; p < 4; p++)
        g_t1[((size_t)bh * L_LM + lb + 4 * p) * DHEAD + d] = acc[p];
}

// ---------------- K8: sim2 + softmax + pinv + t2 ----------------
#define MM16(Cm, Am, Bm)                                        \
    {                                                           \
        float r_ = 0.f;                                         \
        _Pragma("unroll") for (int kk_ = 0; kk_ < 16; kk_++)    \
            r_ += Am[i][kk_] * Bm[kk_][j];                      \
        __syncthreads();                                        \
        Cm[i][j] = r_;                                          \
        __syncthreads();                                        \
    }

__global__ void k_pinv() {
    int bh = blockIdx.x;
    int tid = threadIdx.x;
    int i = tid >> 4, j = tid & 15;
    __shared__ float X[16][16], Z[16][16], XZ[16][16], T[16][16], U[16][16];
    __shared__ float t1s[16][64];
    __shared__ float sden;
    {
        const float* qi = &g_ql[(bh * L_LM + i) * DHEAD];
        const float* kj = &g_kl[(bh * L_LM + j) * DHEAD];
        float s = 0.f;
#pragma unroll
        for (int kk = 0; kk < DHEAD; kk++) s += qi[kk] * kj[kk];
        X[i][j] = s;
    }
    __syncthreads();
    if (tid < 16) {
        float mx = -1e30f;
#pragma unroll
        for (int c = 0; c < 16; c++) mx = fmaxf(mx, X[tid][c]);
        float sm = 0.f;
#pragma unroll
        for (int c = 0; c < 16; c++) { float e = __expf(X[tid][c] - mx); X[tid][c] = e; sm += e; }
        float inv = 1.f / sm;
#pragma unroll
        for (int c = 0; c < 16; c++) X[tid][c] *= inv;
    }
    __syncthreads();
    if (tid == 0) {
        float mc = 0.f, mr = 0.f;
        for (int r = 0; r < 16; r++) {
            float s = 0.f;
            for (int c = 0; c < 16; c++) s += fabsf(X[r][c]);
            mc = fmaxf(mc, s);
        }
        for (int c = 0; c < 16; c++) {
            float s = 0.f;
            for (int r = 0; r < 16; r++) s += fabsf(X[r][c]);
            mr = fmaxf(mr, s);
        }
        float den = mc * mr;
        sden = (den == 0.f) ? 1e-8f : den;
    }
    __syncthreads();
    Z[i][j] = X[j][i] / sden;
    __syncthreads();
    for (int it = 0; it < 6; it++) {
        MM16(XZ, X, Z);
        T[i][j] = (i == j ? 7.f : 0.f) - XZ[i][j];
        __syncthreads();
        MM16(U, XZ, T);
        T[i][j] = (i == j ? 15.f : 0.f) - U[i][j];
        __syncthreads();
        MM16(U, XZ, T);
        T[i][j] = (i == j ? 13.f : 0.f) - U[i][j];
        __syncthreads();
        MM16(U, Z, T);
        Z[i][j] = 0.25f * U[i][j];
        __syncthreads();
    }
    for (int p = tid; p < L_LM * DHEAD; p += 256)
        ((float*)t1s)[p] = g_t1[(size_t)bh * L_LM * DHEAD + p];
    __syncthreads();
#pragma unroll
    for (int p = 0; p < 4; p++) {
        int idx = tid + 256 * p;
        int l = idx >> 6, d = idx & 63;
        float r = 0.f;
#pragma unroll
        for (int kk = 0; kk < 16; kk++) r += Z[l][kk] * t1s[kk][d];
        g_t2[(size_t)bh * L_LM * DHEAD + idx] = r;
    }
}

// ---------------- K9: attn_out = rearrange(attn1 @ t2 + v), tf32-rounded ------
__global__ void k_attnout() {
    int bh = blockIdx.x;
    int b = bh >> 3, h = bh & 7;
    int row = blockIdx.y * 4 + (threadIdx.x >> 6);
    int d = threadIdx.x & 63;
    __shared__ float t2s[L_LM][DHEAD];
    for (int i = threadIdx.x; i < L_LM * DHEAD; i += 256)
        ((float*)t2s)[i] = g_t2[(size_t)bh * L_LM * DHEAD + i];
    __syncthreads();
    const float* a1 = &g_attn1[((size_t)bh * N_SEQ + row) * L_LM];
    float acc = g_qkv[((size_t)(b * N_SEQ + row)) * INNER3 + 2 * DIMC + h * DHEAD + d];
#pragma unroll
    for (int l = 0; l < L_LM; l++) acc += a1[l] * t2s[l][d];
    g_attn_out[((size_t)b * N_SEQ + row) * DIMC + h * DHEAD + d] = to_tf32(acc);
}

// ---------------- launch ----------------
extern "C" void kernel_launch(void* const* d_in, const int* in_sizes, int n_in,
                              void* d_out, int out_size) {
    const float* x     = (const float*)d_in[0];
    const float* ln_g  = (const float*)d_in[1];
    const float* ln_b  = (const float*)d_in[2];
    const float* w_qkv = (const float*)d_in[3];
    const float* w_out = (const float*)d_in[4];
    const float* b_out = (const float*)d_in[5];
    float* out = (float*)d_out;

    cudaFuncSetAttribute(k_gemm_mma<INNER3, false>,
                         cudaFuncAttributeMaxDynamicSharedMemorySize, GEMM_SMEM);
    cudaFuncSetAttribute(k_gemm_mma<DIMC, true>,
                         cudaFuncAttributeMaxDynamicSharedMemorySize, GEMM_SMEM);

    float *wq32, *wo32, *nrm, *ao;
    cudaGetSymbolAddress((void**)&wq32, g_wq32);
    cudaGetSymbolAddress((void**)&wo32, g_wo32);
    cudaGetSymbolAddress((void**)&nrm, g_nrm);
    cudaGetSymbolAddress((void**)&ao, g_attn_out);
    float* qkv;
    cudaGetSymbolAddress((void**)&qkv, g_qkv);

    k_prep_tf32<<<(DIMC * INNER3) / 256, 256>>>(w_qkv, wq32);
    k_prep_tf32<<<(DIMC * DIMC) / 256, 256>>>(w_out, wo32);
    k_layernorm<<<ROWS / 8, dim3(32, 8)>>>(x, ln_g, ln_b);
    k_gemm_mma<INNER3, false><<<dim3(INNER3 / 128, ROWS / 128), 256, GEMM_SMEM>>>(
        nrm, wq32, nullptr, nullptr, qkv);
    k_landmarks<<<2048, 256>>>();
    k_sim1<<<dim3(BH, N_SEQ / 256), 256>>>();
    k_sim3<<<dim3(BH, N_SEQ / 256), 256>>>();
    k_softmax_rows<<<BH * L_LM, 256>>>();
    k_t1<<<BH, 256>>>();
    k_pinv<<<BH, 256>>>();
    k_attnout<<<dim3(BH, N_SEQ / 4), 256>>>();
    k_gemm_mma<DIMC, true><<<dim3(DIMC / 128, ROWS / 128), 256, GEMM_SMEM>>>(
        ao, wo32, x, b_out, out);
}

// round 8
// speedup vs baseline: 2.4943x; 1.1169x over previous
#include <cuda_runtime.h>
#include <math.h>
#include <mma.h>
#include <cstdint>

// ---------------- problem constants ----------------
#define B_SZ   8
#define N_SEQ  4096
#define DIMC   512
#define HEADS  8
#define DHEAD  64
#define M_LM   256
#define L_LM   16
#define BH     64
#define ROWS   32768
#define INNER3 1536
#define SCALE_Q 0.125f
#define LN_EPS 1e-5f

// ---------------- device scratch ----------------
__device__ float g_nrm[(size_t)ROWS * DIMC];          // 64 MB (tf32-rounded)
__device__ float g_qkv[(size_t)ROWS * INNER3];        // 192 MB
__device__ float g_attn_out[(size_t)ROWS * DIMC];     // 64 MB (tf32-rounded)
__device__ float g_wq32[DIMC * INNER3];               // 3 MB tf32-rounded w_qkv
__device__ float g_wo32[DIMC * DIMC];                 // 1 MB tf32-rounded w_out
__device__ float g_ql[BH * L_LM * DHEAD];
__device__ float g_kl[BH * L_LM * DHEAD];
__device__ float g_attn1[(size_t)BH * N_SEQ * L_LM];  // 16 MB
__device__ float g_sim3[(size_t)BH * L_LM * N_SEQ];   // 16 MB
__device__ float g_t1p[BH * 8 * L_LM * DHEAD];        // 8-way partial t1
__device__ float g_t2[BH * L_LM * DHEAD];

// ---------------- helpers ----------------
__device__ __forceinline__ uint32_t smem_u32(const void* p) {
    uint32_t a;
    asm("{ .reg .u64 t; cvta.to.shared.u64 t, %1; cvt.u32.u64 %0, t; }" : "=r"(a) : "l"(p));
    return a;
}
#define CP_ASYNC16(dst, src) \
    asm volatile("cp.async.cg.shared.global [%0], [%1], 16;" :: "r"(dst), "l"(src))
#define CP_COMMIT() asm volatile("cp.async.commit_group;" ::: "memory")
#define CP_WAIT(n)  asm volatile("cp.async.wait_group %0;" :: "n"(n) : "memory")

#define MMA_TF32(c, a, b)                                                       \
    asm volatile("mma.sync.aligned.m16n8k8.row.col.f32.tf32.tf32.f32 "          \
        "{%0,%1,%2,%3}, {%4,%5,%6,%7}, {%8,%9}, {%0,%1,%2,%3};"                 \
        : "+f"((c)[0]), "+f"((c)[1]), "+f"((c)[2]), "+f"((c)[3])                \
        : "r"((a)[0]), "r"((a)[1]), "r"((a)[2]), "r"((a)[3]),                   \
          "r"((b)[0]), "r"((b)[1]))

__device__ __forceinline__ float to_tf32(float v) {
    uint32_t r;
    asm("cvt.rna.tf32.f32 %0, %1;" : "=r"(r) : "f"(v));
    return __uint_as_float(r);
}

// ---------------- K0: tf32-round weights ----------------
__global__ void k_prep_tf32(const float* __restrict__ src, float* __restrict__ dst) {
    int i = blockIdx.x * 256 + threadIdx.x;
    dst[i] = to_tf32(src[i]);
}

// ---------------- K1: LayerNorm -> tf32-rounded fp32 ----------------
__global__ void k_layernorm(const float* __restrict__ x,
                            const float* __restrict__ gamma,
                            const float* __restrict__ beta) {
    int row = blockIdx.x * 8 + threadIdx.y;
    const float4* xr = (const float4*)(x + (size_t)row * DIMC);
    float4 v[4];
    float s = 0.f, ss = 0.f;
#pragma unroll
    for (int i = 0; i < 4; i++) {
        v[i] = xr[threadIdx.x + 32 * i];
        s  += v[i].x + v[i].y + v[i].z + v[i].w;
        ss += v[i].x * v[i].x + v[i].y * v[i].y + v[i].z * v[i].z + v[i].w * v[i].w;
    }
#pragma unroll
    for (int o = 16; o > 0; o >>= 1) {
        s  += __shfl_xor_sync(0xffffffffu, s, o);
        ss += __shfl_xor_sync(0xffffffffu, ss, o);
    }
    float mean = s * (1.f / DIMC);
    float var  = ss * (1.f / DIMC) - mean * mean;
    float rstd = rsqrtf(var + LN_EPS);
    float4* yr = (float4*)(g_nrm + (size_t)row * DIMC);
    const float4* gr = (const float4*)gamma;
    const float4* br = (const float4*)beta;
#pragma unroll
    for (int i = 0; i < 4; i++) {
        int c = threadIdx.x + 32 * i;
        float4 g4 = gr[c], b4 = br[c], o4;
        o4.x = to_tf32((v[i].x - mean) * rstd * g4.x + b4.x);
        o4.y = to_tf32((v[i].y - mean) * rstd * g4.y + b4.y);
        o4.z = to_tf32((v[i].z - mean) * rstd * g4.z + b4.z);
        o4.w = to_tf32((v[i].w - mean) * rstd * g4.w + b4.w);
        yr[c] = o4;
    }
}

// ---------------- mma.sync TF32 GEMM ----------------
// C[ROWS][NTOT] = A[ROWS][512] @ B[512][NTOT]
// Block tile 256x128, warp tile 64x64 (8 warps 4x2), BK=32, 4-stage cp.async.
#define NCHUNK 16
#define NSTAGE 4
#define A_LD 36
#define B_LD 136                 // 136 % 32 == 8 -> conflict-free B frag reads
#define A_ST (256 * A_LD)
#define B_ST (32 * B_LD)
#define GEMM_SMEM (NSTAGE * (A_ST + B_ST) * 4)

template <int NTOT, bool IS_OUT>
__global__ __launch_bounds__(256, 1) void k_gemm_mma(
    const float* __restrict__ A, const float* __restrict__ Bw,
    const float* __restrict__ xres, const float* __restrict__ bias,
    float* __restrict__ C) {
    extern __shared__ float sm[];
    float* AsBase = sm;
    float* BsBase = sm + NSTAGE * A_ST;
    const int tid = threadIdx.x;
    const int warp = tid >> 5, lane = tid & 31;
    const int wm = warp >> 1, wn = warp & 1;
    const int bm = blockIdx.y * 256, bn = blockIdx.x * 128;
    const int g = lane >> 2, q = lane & 3;

    float acc[4][8][4];
#pragma unroll
    for (int mt = 0; mt < 4; mt++)
#pragma unroll
        for (int nt = 0; nt < 8; nt++)
#pragma unroll
            for (int e = 0; e < 4; e++) acc[mt][nt][e] = 0.f;

    auto load_chunk = [&](int c) {
        int st = c & 3;
        float* as = AsBase + st * A_ST;
        float* bs = BsBase + st * B_ST;
        int k0 = c * 32;
#pragma unroll
        for (int t = 0; t < 8; t++) {
            int idx = tid + t * 256;
            int arow = idx >> 3, aseg = idx & 7;
            CP_ASYNC16(smem_u32(as + arow * A_LD + aseg * 4),
                       A + (size_t)(bm + arow) * DIMC + k0 + aseg * 4);
        }
#pragma unroll
        for (int t = 0; t < 4; t++) {
            int idx = tid + t * 256;
            int brow = idx >> 5, bseg = idx & 31;
            CP_ASYNC16(smem_u32(bs + brow * B_LD + bseg * 4),
                       Bw + (size_t)(k0 + brow) * NTOT + bn + bseg * 4);
        }
        CP_COMMIT();
    };

    load_chunk(0);
    load_chunk(1);
    load_chunk(2);

    for (int c = 0; c < NCHUNK; c++) {
        if (c <= NCHUNK - 3)      { CP_WAIT(2); }
        else if (c == NCHUNK - 2) { CP_WAIT(1); }
        else                      { CP_WAIT(0); }
        __syncthreads();
        if (c + 3 < NCHUNK) load_chunk(c + 3);

        int st = c & 3;
        const float* as = AsBase + st * A_ST + (wm * 64 + g) * A_LD + q;
        const float* bs = BsBase + st * B_ST + q * B_LD + wn * 64 + g;
#pragma unroll
        for (int kk = 0; kk < 32; kk += 8) {
            uint32_t af[4][4], bf[8][2];
#pragma unroll
            for (int mt = 0; mt < 4; mt++) {
                const float* p = as + mt * 16 * A_LD + kk;
                af[mt][0] = __float_as_uint(p[0]);
                af[mt][1] = __float_as_uint(p[8 * A_LD]);
                af[mt][2] = __float_as_uint(p[4]);
                af[mt][3] = __float_as_uint(p[8 * A_LD + 4]);
            }
            {
                const float* p = bs + kk * B_LD;
#pragma unroll
                for (int nt = 0; nt < 8; nt++) {
                    bf[nt][0] = __float_as_uint(p[nt * 8]);
                    bf[nt][1] = __float_as_uint(p[4 * B_LD + nt * 8]);
                }
            }
#pragma unroll
            for (int mt = 0; mt < 4; mt++)
#pragma unroll
                for (int nt = 0; nt < 8; nt++)
                    MMA_TF32(acc[mt][nt], af[mt], bf[nt]);
        }
    }

    // epilogue: direct register -> global float2 stores
#pragma unroll
    for (int mt = 0; mt < 4; mt++) {
        int row0 = bm + wm * 64 + mt * 16 + g;
#pragma unroll
        for (int nt = 0; nt < 8; nt++) {
            int col = bn + wn * 64 + nt * 8 + 2 * q;
            float* c = acc[mt][nt];
            if (IS_OUT) {
                size_t o0 = (size_t)row0 * NTOT + col;
                size_t o1 = (size_t)(row0 + 8) * NTOT + col;
                float2 bv = *(const float2*)&bias[col];
                float2 x0 = *(const float2*)&xres[o0];
                float2 x1 = *(const float2*)&xres[o1];
                *(float2*)&C[o0] = make_float2(c[0] + x0.x + bv.x, c[1] + x0.y + bv.y);
                *(float2*)&C[o1] = make_float2(c[2] + x1.x + bv.x, c[3] + x1.y + bv.y);
            } else {
                float sc = (col < 512) ? SCALE_Q : 1.f;
                size_t o0 = (size_t)row0 * NTOT + col;
                size_t o1 = (size_t)(row0 + 8) * NTOT + col;
                *(float2*)&C[o0] = make_float2(c[0] * sc, c[1] * sc);
                *(float2*)&C[o1] = make_float2(c[2] * sc, c[3] * sc);
            }
        }
    }
}

// ---------------- K3: landmark means ----------------
__global__ void k_landmarks() {
    int id = blockIdx.x;
    int which = id >> 10;
    int bhl = id & 1023;
    int bh = bhl >> 4, l = bhl & 15;
    int b = bh >> 3, h = bh & 7;
    float* dst = which ? g_kl : g_ql;
    int d = threadIdx.x & 63, part = threadIdx.x >> 6;
    size_t base = ((size_t)(b * N_SEQ + l * M_LM + part * 64)) * INNER3 +
                  which * DIMC + h * DHEAD + d;
    float s = 0.f;
#pragma unroll 8
    for (int j = 0; j < 64; j++) s += g_qkv[base + (size_t)j * INNER3];
    __shared__ float red[4][64];
    red[part][d] = s;
    __syncthreads();
    if (part == 0)
        dst[(bh * L_LM + l) * DHEAD + d] =
            (red[0][d] + red[1][d] + red[2][d] + red[3][d]) * (1.f / M_LM);
}

// ---------------- K4: attn1 = softmax(q @ k_l^T) ----------------
__global__ void k_sim1() {
    int bh = blockIdx.x;
    int b = bh >> 3, h = bh & 7;
    int row = blockIdx.y * 256 + threadIdx.x;
    __shared__ float kls[L_LM][DHEAD];
    for (int i = threadIdx.x; i < L_LM * DHEAD; i += 256)
        kls[i >> 6][i & 63] = g_kl[bh * L_LM * DHEAD + i];
    __syncthreads();
    const float* qrow = &g_qkv[((size_t)(b * N_SEQ + row)) * INNER3 + h * DHEAD];
    float s[L_LM];
#pragma unroll
    for (int l = 0; l < L_LM; l++) s[l] = 0.f;
    for (int kk = 0; kk < DHEAD; kk += 4) {
        float4 qv = *(const float4*)&qrow[kk];
#pragma unroll
        for (int l = 0; l < L_LM; l++)
            s[l] += qv.x * kls[l][kk] + qv.y * kls[l][kk + 1] +
                    qv.z * kls[l][kk + 2] + qv.w * kls[l][kk + 3];
    }
    float mx = s[0];
#pragma unroll
    for (int l = 1; l < L_LM; l++) mx = fmaxf(mx, s[l]);
    float sum = 0.f;
#pragma unroll
    for (int l = 0; l < L_LM; l++) { s[l] = __expf(s[l] - mx); sum += s[l]; }
    float inv = 1.f / sum;
    float* dst = &g_attn1[((size_t)bh * N_SEQ + row) * L_LM];
#pragma unroll
    for (int l = 0; l < L_LM; l += 4)
        *(float4*)&dst[l] = make_float4(s[l] * inv, s[l + 1] * inv, s[l + 2] * inv, s[l + 3] * inv);
}

// ---------------- K5: sim3 = q_l @ k^T ----------------
__global__ void k_sim3() {
    int bh = blockIdx.x;
    int b = bh >> 3, h = bh & 7;
    int j = blockIdx.y * 256 + threadIdx.x;
    __shared__ float qls[L_LM][DHEAD];
    for (int i = threadIdx.x; i < L_LM * DHEAD; i += 256)
        qls[i >> 6][i & 63] = g_ql[bh * L_LM * DHEAD + i];
    __syncthreads();
    const float* krow = &g_qkv[((size_t)(b * N_SEQ + j)) * INNER3 + DIMC + h * DHEAD];
    float s[L_LM];
#pragma unroll
    for (int l = 0; l < L_LM; l++) s[l] = 0.f;
    for (int kk = 0; kk < DHEAD; kk += 4) {
        float4 kv = *(const float4*)&krow[kk];
#pragma unroll
        for (int l = 0; l < L_LM; l++)
            s[l] += kv.x * qls[l][kk] + kv.y * qls[l][kk + 1] +
                    kv.z * qls[l][kk + 2] + kv.w * qls[l][kk + 3];
    }
#pragma unroll
    for (int l = 0; l < L_LM; l++)
        g_sim3[((size_t)bh * L_LM + l) * N_SEQ + j] = s[l];
}

// ---------------- K6: softmax over rows of 4096 ----------------
__global__ void k_softmax_rows() {
    __shared__ float red[8];
    float* row = g_sim3 + (size_t)blockIdx.x * N_SEQ;
    int t = threadIdx.x, lane = t & 31, warp = t >> 5;
    float v[16];
    float mx = -1e30f;
#pragma unroll
    for (int i = 0; i < 16; i++) { v[i] = row[t + 256 * i]; mx = fmaxf(mx, v[i]); }
#pragma unroll
    for (int o = 16; o > 0; o >>= 1) mx = fmaxf(mx, __shfl_xor_sync(0xffffffffu, mx, o));
    if (lane == 0) red[warp] = mx;
    __syncthreads();
    mx = red[0];
#pragma unroll
    for (int w = 1; w < 8; w++) mx = fmaxf(mx, red[w]);
    __syncthreads();
    float sum = 0.f;
#pragma unroll
    for (int i = 0; i < 16; i++) { v[i] = __expf(v[i] - mx); sum += v[i]; }
#pragma unroll
    for (int o = 16; o > 0; o >>= 1) sum += __shfl_xor_sync(0xffffffffu, sum, o);
    if (lane == 0) red[warp] = sum;
    __syncthreads();
    sum = 0.f;
#pragma unroll
    for (int w = 0; w < 8; w++) sum += red[w];
    float inv = 1.f / sum;
#pragma unroll
    for (int i = 0; i < 16; i++) row[t + 256 * i] = v[i] * inv;
}

// ---------------- K7: t1 partials = attn3 @ v (8-way split over seq) ---------
__global__ void k_t1() {
    int bh = blockIdx.x;
    int part = blockIdx.y;                 // 0..7, 512 seq positions each
    int b = bh >> 3, h = bh & 7;
    __shared__ float a_s[L_LM][128];
    __shared__ float v_s[128][DHEAD];
    int d = threadIdx.x & 63;
    int lb = threadIdx.x >> 6;
    float acc[4] = {0.f, 0.f, 0.f, 0.f};
    for (int j0 = part * 512; j0 < part * 512 + 512; j0 += 128) {
        for (int i = threadIdx.x; i < L_LM * 128; i += 256) {
            int l = i >> 7, jj = i & 127;
            a_s[l][jj] = g_sim3[((size_t)bh * L_LM + l) * N_SEQ + j0 + jj];
        }
        for (int i = threadIdx.x; i < 128 * 16; i += 256) {
            int row = i >> 4, d4 = i & 15;
            *(float4*)&v_s[row][d4 * 4] =
                *(const float4*)&g_qkv[((size_t)(b * N_SEQ + j0 + row)) * INNER3 +
                                       2 * DIMC + h * DHEAD + d4 * 4];
        }
        __syncthreads();
        for (int jj = 0; jj < 128; jj++) {
            float vv = v_s[jj][d];
#pragma unroll
            for (int p = 0; p < 4; p++) acc[p] += a_s[lb + 4 * p][jj] * vv;
        }
        __syncthreads();
    }
#pragma unroll
    for (int p = 0; p < 4; p++)
        g_t1p[((size_t)(bh * 8 + part) * L_LM + lb + 4 * p) * DHEAD + d] = acc[p];
}

// ---------------- K8: sim2 + softmax + pinv + t2 ----------------
#define MM16(Cm, Am, Bm)                                        \
    {                                                           \
        float r_ = 0.f;                                         \
        _Pragma("unroll") for (int kk_ = 0; kk_ < 16; kk_++)    \
            r_ += Am[i][kk_] * Bm[kk_][j];                      \
        __syncthreads();                                        \
        Cm[i][j] = r_;                                          \
        __syncthreads();                                        \
    }

__global__ void k_pinv() {
    int bh = blockIdx.x;
    int tid = threadIdx.x;
    int i = tid >> 4, j = tid & 15;
    __shared__ float X[16][16], Z[16][16], XZ[16][16], T[16][16], U[16][16];
    __shared__ float t1s[16][64];
    __shared__ float sden;
    {
        const float* qi = &g_ql[(bh * L_LM + i) * DHEAD];
        const float* kj = &g_kl[(bh * L_LM + j) * DHEAD];
        float s = 0.f;
#pragma unroll
        for (int kk = 0; kk < DHEAD; kk++) s += qi[kk] * kj[kk];
        X[i][j] = s;
    }
    __syncthreads();
    if (tid < 16) {
        float mx = -1e30f;
#pragma unroll
        for (int c = 0; c < 16; c++) mx = fmaxf(mx, X[tid][c]);
        float sm = 0.f;
#pragma unroll
        for (int c = 0; c < 16; c++) { float e = __expf(X[tid][c] - mx); X[tid][c] = e; sm += e; }
        float inv = 1.f / sm;
#pragma unroll
        for (int c = 0; c < 16; c++) X[tid][c] *= inv;
    }
    __syncthreads();
    if (tid == 0) {
        float mc = 0.f, mr = 0.f;
        for (int r = 0; r < 16; r++) {
            float s = 0.f;
            for (int c = 0; c < 16; c++) s += fabsf(X[r][c]);
            mc = fmaxf(mc, s);
        }
        for (int c = 0; c < 16; c++) {
            float s = 0.f;
            for (int r = 0; r < 16; r++) s += fabsf(X[r][c]);
            mr = fmaxf(mr, s);
        }
        float den = mc * mr;
        sden = (den == 0.f) ? 1e-8f : den;
    }
    __syncthreads();
    Z[i][j] = X[j][i] / sden;
    __syncthreads();
    for (int it = 0; it < 6; it++) {
        MM16(XZ, X, Z);
        T[i][j] = (i == j ? 7.f : 0.f) - XZ[i][j];
        __syncthreads();
        MM16(U, XZ, T);
        T[i][j] = (i == j ? 15.f : 0.f) - U[i][j];
        __syncthreads();
        MM16(U, XZ, T);
        T[i][j] = (i == j ? 13.f : 0.f) - U[i][j];
        __syncthreads();
        MM16(U, Z, T);
        Z[i][j] = 0.25f * U[i][j];
        __syncthreads();
    }
    // reduce 8-way t1 partials into t1s
    for (int p = tid; p < L_LM * DHEAD; p += 256) {
        float s = 0.f;
#pragma unroll
        for (int pp = 0; pp < 8; pp++)
            s += g_t1p[(size_t)(bh * 8 + pp) * L_LM * DHEAD + p];
        ((float*)t1s)[p] = s;
    }
    __syncthreads();
#pragma unroll
    for (int p = 0; p < 4; p++) {
        int idx = tid + 256 * p;
        int l = idx >> 6, d = idx & 63;
        float r = 0.f;
#pragma unroll
        for (int kk = 0; kk < 16; kk++) r += Z[l][kk] * t1s[kk][d];
        g_t2[(size_t)bh * L_LM * DHEAD + idx] = r;
    }
}

// ---------------- K9: attn_out = rearrange(attn1 @ t2 + v), tf32-rounded ------
__global__ void k_attnout() {
    int bh = blockIdx.x;
    int b = bh >> 3, h = bh & 7;
    int row = blockIdx.y * 4 + (threadIdx.x >> 6);
    int d = threadIdx.x & 63;
    __shared__ float t2s[L_LM][DHEAD];
    for (int i = threadIdx.x; i < L_LM * DHEAD; i += 256)
        ((float*)t2s)[i] = g_t2[(size_t)bh * L_LM * DHEAD + i];
    __syncthreads();
    const float* a1 = &g_attn1[((size_t)bh * N_SEQ + row) * L_LM];
    float acc = g_qkv[((size_t)(b * N_SEQ + row)) * INNER3 + 2 * DIMC + h * DHEAD + d];
#pragma unroll
    for (int l = 0; l < L_LM; l++) acc += a1[l] * t2s[l][d];
    g_attn_out[((size_t)b * N_SEQ + row) * DIMC + h * DHEAD + d] = to_tf32(acc);
}

// ---------------- launch ----------------
extern "C" void kernel_launch(void* const* d_in, const int* in_sizes, int n_in,
                              void* d_out, int out_size) {
    const float* x     = (const float*)d_in[0];
    const float* ln_g  = (const float*)d_in[1];
    const float* ln_b  = (const float*)d_in[2];
    const float* w_qkv = (const float*)d_in[3];
    const float* w_out = (const float*)d_in[4];
    const float* b_out = (const float*)d_in[5];
    float* out = (float*)d_out;

    cudaFuncSetAttribute(k_gemm_mma<INNER3, false>,
                         cudaFuncAttributeMaxDynamicSharedMemorySize, GEMM_SMEM);
    cudaFuncSetAttribute(k_gemm_mma<DIMC, true>,
                         cudaFuncAttributeMaxDynamicSharedMemorySize, GEMM_SMEM);

    float *wq32, *wo32, *nrm, *ao;
    cudaGetSymbolAddress((void**)&wq32, g_wq32);
    cudaGetSymbolAddress((void**)&wo32, g_wo32);
    cudaGetSymbolAddress((void**)&nrm, g_nrm);
    cudaGetSymbolAddress((void**)&ao, g_attn_out);
    float* qkv;
    cudaGetSymbolAddress((void**)&qkv, g_qkv);

    k_prep_tf32<<<(DIMC * INNER3) / 256, 256>>>(w_qkv, wq32);
    k_prep_tf32<<<(DIMC * DIMC) / 256, 256>>>(w_out, wo32);
    k_layernorm<<<ROWS / 8, dim3(32, 8)>>>(x, ln_g, ln_b);
    k_gemm_mma<INNER3, false><<<dim3(INNER3 / 128, ROWS / 256), 256, GEMM_SMEM>>>(
        nrm, wq32, nullptr, nullptr, qkv);
    k_landmarks<<<2048, 256>>>();
    k_sim1<<<dim3(BH, N_SEQ / 256), 256>>>();
    k_sim3<<<dim3(BH, N_SEQ / 256), 256>>>();
    k_softmax_rows<<<BH * L_LM, 256>>>();
    k_t1<<<dim3(BH, 8), 256>>>();
    k_pinv<<<BH, 256>>>();
    k_attnout<<<dim3(BH, N_SEQ / 4), 256>>>();
    k_gemm_mma<DIMC, true><<<dim3(DIMC / 128, ROWS / 256), 256, GEMM_SMEM>>>(
        ao, wo32, x, b_out, out);
}

// round 9
// speedup vs baseline: 3.1624x; 1.2678x over previous
#include <cuda_runtime.h>
#include <cuda_fp16.h>
#include <math.h>
#include <cstdint>

// ---------------- problem constants ----------------
#define B_SZ   8
#define N_SEQ  4096
#define DIMC   512
#define HEADS  8
#define DHEAD  64
#define M_LM   256
#define L_LM   16
#define BH     64
#define ROWS   32768
#define INNER3 1536
#define SCALE_Q 0.125f
#define LN_EPS 1e-5f

// ---------------- device scratch ----------------
__device__ __half g_nrm_h[(size_t)ROWS * DIMC];       // 32 MB LN output (fp16)
__device__ float  g_qkv[(size_t)ROWS * INNER3];       // 192 MB
__device__ __half g_ao_h[(size_t)ROWS * DIMC];        // 32 MB attn_out (fp16)
__device__ __half g_wqh[INNER3 * DIMC];               // w_qkv^T [1536][512] fp16
__device__ __half g_woh[DIMC * DIMC];                 // w_out^T [512][512] fp16
__device__ float g_ql[BH * L_LM * DHEAD];
__device__ float g_kl[BH * L_LM * DHEAD];
__device__ float g_attn1[(size_t)BH * N_SEQ * L_LM];  // 16 MB
__device__ float g_sim3[(size_t)BH * L_LM * N_SEQ];   // 16 MB
__device__ float g_t1p[BH * 8 * L_LM * DHEAD];        // 8-way partial t1
__device__ float g_t2[BH * L_LM * DHEAD];

// ---------------- helpers ----------------
__device__ __forceinline__ uint32_t smem_u32(const void* p) {
    uint32_t a;
    asm("{ .reg .u64 t; cvta.to.shared.u64 t, %1; cvt.u32.u64 %0, t; }" : "=r"(a) : "l"(p));
    return a;
}
#define CP_ASYNC16(dst, src) \
    asm volatile("cp.async.cg.shared.global [%0], [%1], 16;" :: "r"(dst), "l"(src))
#define CP_COMMIT() asm volatile("cp.async.commit_group;" ::: "memory")
#define CP_WAIT(n)  asm volatile("cp.async.wait_group %0;" :: "n"(n) : "memory")

#define MMA_F16(c, a, b)                                                        \
    asm volatile("mma.sync.aligned.m16n8k16.row.col.f32.f16.f16.f32 "           \
        "{%0,%1,%2,%3}, {%4,%5,%6,%7}, {%8,%9}, {%0,%1,%2,%3};"                 \
        : "+f"((c)[0]), "+f"((c)[1]), "+f"((c)[2]), "+f"((c)[3])                \
        : "r"((a)[0]), "r"((a)[1]), "r"((a)[2]), "r"((a)[3]),                   \
          "r"((b)[0]), "r"((b)[1]))

// ---------------- K0: weight transpose + fp16 convert (tiled) ----------------
// W: [512][N] fp32 row-major  ->  Wh: [N][512] fp16
__global__ void k_prep_wh(const float* __restrict__ W, __half* __restrict__ Wh, int N) {
    __shared__ float t[32][33];
    int n0 = blockIdx.x * 32, k0 = blockIdx.y * 32;
    int tx = threadIdx.x, ty = threadIdx.y;
#pragma unroll
    for (int j = 0; j < 4; j++)
        t[ty + 8 * j][tx] = W[(size_t)(k0 + ty + 8 * j) * N + n0 + tx];
    __syncthreads();
#pragma unroll
    for (int j = 0; j < 4; j++)
        Wh[(size_t)(n0 + ty + 8 * j) * DIMC + k0 + tx] = __float2half(t[tx][ty + 8 * j]);
}

// ---------------- K1: LayerNorm -> fp16 ----------------
__global__ void k_layernorm(const float* __restrict__ x,
                            const float* __restrict__ gamma,
                            const float* __restrict__ beta) {
    int row = blockIdx.x * 8 + threadIdx.y;
    const float4* xr = (const float4*)(x + (size_t)row * DIMC);
    float4 v[4];
    float s = 0.f, ss = 0.f;
#pragma unroll
    for (int i = 0; i < 4; i++) {
        v[i] = xr[threadIdx.x + 32 * i];
        s  += v[i].x + v[i].y + v[i].z + v[i].w;
        ss += v[i].x * v[i].x + v[i].y * v[i].y + v[i].z * v[i].z + v[i].w * v[i].w;
    }
#pragma unroll
    for (int o = 16; o > 0; o >>= 1) {
        s  += __shfl_xor_sync(0xffffffffu, s, o);
        ss += __shfl_xor_sync(0xffffffffu, ss, o);
    }
    float mean = s * (1.f / DIMC);
    float var  = ss * (1.f / DIMC) - mean * mean;
    float rstd = rsqrtf(var + LN_EPS);
    const float4* gr = (const float4*)gamma;
    const float4* br = (const float4*)beta;
    __half2* yr = (__half2*)(g_nrm_h + (size_t)row * DIMC);
#pragma unroll
    for (int i = 0; i < 4; i++) {
        int c = threadIdx.x + 32 * i;
        float4 g4 = gr[c], b4 = br[c];
        float o0 = (v[i].x - mean) * rstd * g4.x + b4.x;
        float o1 = (v[i].y - mean) * rstd * g4.y + b4.y;
        float o2 = (v[i].z - mean) * rstd * g4.z + b4.z;
        float o3 = (v[i].w - mean) * rstd * g4.w + b4.w;
        yr[c * 2]     = __floats2half2_rn(o0, o1);
        yr[c * 2 + 1] = __floats2half2_rn(o2, o3);
    }
}

// ---------------- fp16 mma.sync GEMM ----------------
// C[ROWS][NTOT] = A[ROWS][512] @ B^T, A half [row][k], B half [n][k].
// Block tile 256x128, warp tile 64x64 (8 warps 4x2), BK=32, 4-stage cp.async.
#define NCHUNK 16
#define NSTAGE 4
#define T_LD 40                    // halves per row (conflict-free: 20 words, gcd(20,32) spread)
#define A_ST (256 * T_LD)          // halves per A stage
#define B_ST (128 * T_LD)          // halves per B stage
#define GEMM_SMEM (NSTAGE * (A_ST + B_ST) * 2)

template <int NTOT, bool IS_OUT>
__global__ __launch_bounds__(256, 1) void k_gemm_mma(
    const __half* __restrict__ A, const __half* __restrict__ Bw,
    const float* __restrict__ xres, const float* __restrict__ bias,
    float* __restrict__ C) {
    extern __shared__ __half smh[];
    __half* AsBase = smh;
    __half* BsBase = smh + NSTAGE * A_ST;
    const int tid = threadIdx.x;
    const int warp = tid >> 5, lane = tid & 31;
    const int wm = warp >> 1, wn = warp & 1;
    const int bm = blockIdx.y * 256, bn = blockIdx.x * 128;
    const int g = lane >> 2, q = lane & 3;

    float acc[4][8][4];
#pragma unroll
    for (int mt = 0; mt < 4; mt++)
#pragma unroll
        for (int nt = 0; nt < 8; nt++)
#pragma unroll
            for (int e = 0; e < 4; e++) acc[mt][nt][e] = 0.f;

    auto load_chunk = [&](int c) {
        int st = c & 3;
        __half* as = AsBase + st * A_ST;
        __half* bs = BsBase + st * B_ST;
        int k0 = c * 32;
#pragma unroll
        for (int t = 0; t < 4; t++) {
            int idx = tid + t * 256;           // 0..1023
            int row = idx >> 2, seg = idx & 3; // 256 rows x 4 segs of 8 halves
            CP_ASYNC16(smem_u32(as + row * T_LD + seg * 8),
                       A + (size_t)(bm + row) * DIMC + k0 + seg * 8);
        }
#pragma unroll
        for (int t = 0; t < 2; t++) {
            int idx = tid + t * 256;           // 0..511
            int row = idx >> 2, seg = idx & 3; // 128 rows x 4 segs
            CP_ASYNC16(smem_u32(bs + row * T_LD + seg * 8),
                       Bw + (size_t)(bn + row) * DIMC + k0 + seg * 8);
        }
        CP_COMMIT();
    };

    load_chunk(0);
    load_chunk(1);
    load_chunk(2);

    for (int c = 0; c < NCHUNK; c++) {
        if (c <= NCHUNK - 3)      { CP_WAIT(2); }
        else if (c == NCHUNK - 2) { CP_WAIT(1); }
        else                      { CP_WAIT(0); }
        __syncthreads();
        if (c + 3 < NCHUNK) load_chunk(c + 3);

        int st = c & 3;
        const __half* as = AsBase + st * A_ST + (wm * 64 + g) * T_LD + 2 * q;
        const __half* bs = BsBase + st * B_ST + (wn * 64 + g) * T_LD + 2 * q;
#pragma unroll
        for (int ks = 0; ks < 2; ks++) {       // two K=16 steps per 32-chunk
            int ko = ks * 16;
            uint32_t af[4][4], bf[8][2];
#pragma unroll
            for (int mt = 0; mt < 4; mt++) {
                const __half* p = as + mt * 16 * T_LD + ko;
                af[mt][0] = *(const uint32_t*)(p);
                af[mt][1] = *(const uint32_t*)(p + 8 * T_LD);
                af[mt][2] = *(const uint32_t*)(p + 8);
                af[mt][3] = *(const uint32_t*)(p + 8 * T_LD + 8);
            }
#pragma unroll
            for (int nt = 0; nt < 8; nt++) {
                const __half* p = bs + nt * 8 * T_LD + ko;
                bf[nt][0] = *(const uint32_t*)(p);
                bf[nt][1] = *(const uint32_t*)(p + 8);
            }
#pragma unroll
            for (int mt = 0; mt < 4; mt++)
#pragma unroll
                for (int nt = 0; nt < 8; nt++)
                    MMA_F16(acc[mt][nt], af[mt], bf[nt]);
        }
    }

    // epilogue: direct register -> global float2 stores
#pragma unroll
    for (int mt = 0; mt < 4; mt++) {
        int row0 = bm + wm * 64 + mt * 16 + g;
#pragma unroll
        for (int nt = 0; nt < 8; nt++) {
            int col = bn + wn * 64 + nt * 8 + 2 * q;
            float* c = acc[mt][nt];
            if (IS_OUT) {
                size_t o0 = (size_t)row0 * NTOT + col;
                size_t o1 = (size_t)(row0 + 8) * NTOT + col;
                float2 bv = *(const float2*)&bias[col];
                float2 x0 = *(const float2*)&xres[o0];
                float2 x1 = *(const float2*)&xres[o1];
                *(float2*)&C[o0] = make_float2(c[0] + x0.x + bv.x, c[1] + x0.y + bv.y);
                *(float2*)&C[o1] = make_float2(c[2] + x1.x + bv.x, c[3] + x1.y + bv.y);
            } else {
                float sc = (col < 512) ? SCALE_Q : 1.f;
                size_t o0 = (size_t)row0 * NTOT + col;
                size_t o1 = (size_t)(row0 + 8) * NTOT + col;
                *(float2*)&C[o0] = make_float2(c[0] * sc, c[1] * sc);
                *(float2*)&C[o1] = make_float2(c[2] * sc, c[3] * sc);
            }
        }
    }
}

// ---------------- K3: landmark means ----------------
__global__ void k_landmarks() {
    int id = blockIdx.x;
    int which = id >> 10;
    int bhl = id & 1023;
    int bh = bhl >> 4, l = bhl & 15;
    int b = bh >> 3, h = bh & 7;
    float* dst = which ? g_kl : g_ql;
    int d = threadIdx.x & 63, part = threadIdx.x >> 6;
    size_t base = ((size_t)(b * N_SEQ + l * M_LM + part * 64)) * INNER3 +
                  which * DIMC + h * DHEAD + d;
    float s = 0.f;
#pragma unroll 8
    for (int j = 0; j < 64; j++) s += g_qkv[base + (size_t)j * INNER3];
    __shared__ float red[4][64];
    red[part][d] = s;
    __syncthreads();
    if (part == 0)
        dst[(bh * L_LM + l) * DHEAD + d] =
            (red[0][d] + red[1][d] + red[2][d] + red[3][d]) * (1.f / M_LM);
}

// ---------------- K4: attn1 = softmax(q @ k_l^T) ----------------
__global__ void k_sim1() {
    int bh = blockIdx.x;
    int b = bh >> 3, h = bh & 7;
    int row = blockIdx.y * 256 + threadIdx.x;
    __shared__ float kls[L_LM][DHEAD];
    for (int i = threadIdx.x; i < L_LM * DHEAD; i += 256)
        kls[i >> 6][i & 63] = g_kl[bh * L_LM * DHEAD + i];
    __syncthreads();
    const float* qrow = &g_qkv[((size_t)(b * N_SEQ + row)) * INNER3 + h * DHEAD];
    float s[L_LM];
#pragma unroll
    for (int l = 0; l < L_LM; l++) s[l] = 0.f;
    for (int kk = 0; kk < DHEAD; kk += 4) {
        float4 qv = *(const float4*)&qrow[kk];
#pragma unroll
        for (int l = 0; l < L_LM; l++)
            s[l] += qv.x * kls[l][kk] + qv.y * kls[l][kk + 1] +
                    qv.z * kls[l][kk + 2] + qv.w * kls[l][kk + 3];
    }
    float mx = s[0];
#pragma unroll
    for (int l = 1; l < L_LM; l++) mx = fmaxf(mx, s[l]);
    float sum = 0.f;
#pragma unroll
    for (int l = 0; l < L_LM; l++) { s[l] = __expf(s[l] - mx); sum += s[l]; }
    float inv = 1.f / sum;
    float* dst = &g_attn1[((size_t)bh * N_SEQ + row) * L_LM];
#pragma unroll
    for (int l = 0; l < L_LM; l += 4)
        *(float4*)&dst[l] = make_float4(s[l] * inv, s[l + 1] * inv, s[l + 2] * inv, s[l + 3] * inv);
}

// ---------------- K5: sim3 = q_l @ k^T ----------------
__global__ void k_sim3() {
    int bh = blockIdx.x;
    int b = bh >> 3, h = bh & 7;
    int j = blockIdx.y * 256 + threadIdx.x;
    __shared__ float qls[L_LM][DHEAD];
    for (int i = threadIdx.x; i < L_LM * DHEAD; i += 256)
        qls[i >> 6][i & 63] = g_ql[bh * L_LM * DHEAD + i];
    __syncthreads();
    const float* krow = &g_qkv[((size_t)(b * N_SEQ + j)) * INNER3 + DIMC + h * DHEAD];
    float s[L_LM];
#pragma unroll
    for (int l = 0; l < L_LM; l++) s[l] = 0.f;
    for (int kk = 0; kk < DHEAD; kk += 4) {
        float4 kv = *(const float4*)&krow[kk];
#pragma unroll
        for (int l = 0; l < L_LM; l++)
            s[l] += kv.x * qls[l][kk] + kv.y * qls[l][kk + 1] +
                    kv.z * qls[l][kk + 2] + kv.w * qls[l][kk + 3];
    }
#pragma unroll
    for (int l = 0; l < L_LM; l++)
        g_sim3[((size_t)bh * L_LM + l) * N_SEQ + j] = s[l];
}

// ---------------- K6: softmax over rows of 4096 ----------------
__global__ void k_softmax_rows() {
    __shared__ float red[8];
    float* row = g_sim3 + (size_t)blockIdx.x * N_SEQ;
    int t = threadIdx.x, lane = t & 31, warp = t >> 5;
    float v[16];
    float mx = -1e30f;
#pragma unroll
    for (int i = 0; i < 16; i++) { v[i] = row[t + 256 * i]; mx = fmaxf(mx, v[i]); }
#pragma unroll
    for (int o = 16; o > 0; o >>= 1) mx = fmaxf(mx, __shfl_xor_sync(0xffffffffu, mx, o));
    if (lane == 0) red[warp] = mx;
    __syncthreads();
    mx = red[0];
#pragma unroll
    for (int w = 1; w < 8; w++) mx = fmaxf(mx, red[w]);
    __syncthreads();
    float sum = 0.f;
#pragma unroll
    for (int i = 0; i < 16; i++) { v[i] = __expf(v[i] - mx); sum += v[i]; }
#pragma unroll
    for (int o = 16; o > 0; o >>= 1) sum += __shfl_xor_sync(0xffffffffu, sum, o);
    if (lane == 0) red[warp] = sum;
    __syncthreads();
    sum = 0.f;
#pragma unroll
    for (int w = 0; w < 8; w++) sum += red[w];
    float inv = 1.f / sum;
#pragma unroll
    for (int i = 0; i < 16; i++) row[t + 256 * i] = v[i] * inv;
}

// ---------------- K7: t1 partials = attn3 @ v (8-way split over seq) ---------
__global__ void k_t1() {
    int bh = blockIdx.x;
    int part = blockIdx.y;
    int b = bh >> 3, h = bh & 7;
    __shared__ float a_s[L_LM][128];
    __shared__ float v_s[128][DHEAD];
    int d = threadIdx.x & 63;
    int lb = threadIdx.x >> 6;
    float acc[4] = {0.f, 0.f, 0.f, 0.f};
    for (int j0 = part * 512; j0 < part * 512 + 512; j0 += 128) {
        for (int i = threadIdx.x; i < L_LM * 128; i += 256) {
            int l = i >> 7, jj = i & 127;
            a_s[l][jj] = g_sim3[((size_t)bh * L_LM + l) * N_SEQ + j0 + jj];
        }
        for (int i = threadIdx.x; i < 128 * 16; i += 256) {
            int row = i >> 4, d4 = i & 15;
            *(float4*)&v_s[row][d4 * 4] =
                *(const float4*)&g_qkv[((size_t)(b * N_SEQ + j0 + row)) * INNER3 +
                                       2 * DIMC + h * DHEAD + d4 * 4];
        }
        __syncthreads();
        for (int jj = 0; jj < 128; jj++) {
            float vv = v_s[jj][d];
#pragma unroll
            for (int p = 0; p < 4; p++) acc[p] += a_s[lb + 4 * p][jj] * vv;
        }
        __syncthreads();
    }
#pragma unroll
    for (int p = 0; p < 4; p++)
        g_t1p[((size_t)(bh * 8 + part) * L_LM + lb + 4 * p) * DHEAD + d] = acc[p];
}

// ---------------- K8: sim2 + softmax + pinv + t2 ----------------
#define MM16(Cm, Am, Bm)                                        \
    {                                                           \
        float r_ = 0.f;                                         \
        _Pragma("unroll") for (int kk_ = 0; kk_ < 16; kk_++)    \
            r_ += Am[i][kk_] * Bm[kk_][j];                      \
        __syncthreads();                                        \
        Cm[i][j] = r_;                                          \
        __syncthreads();                                        \
    }

__global__ void k_pinv() {
    int bh = blockIdx.x;
    int tid = threadIdx.x;
    int i = tid >> 4, j = tid & 15;
    __shared__ float X[16][16], Z[16][16], XZ[16][16], T[16][16], U[16][16];
    __shared__ float t1s[16][64];
    __shared__ float sden;
    {
        const float* qi = &g_ql[(bh * L_LM + i) * DHEAD];
        const float* kj = &g_kl[(bh * L_LM + j) * DHEAD];
        float s = 0.f;
#pragma unroll
        for (int kk = 0; kk < DHEAD; kk++) s += qi[kk] * kj[kk];
        X[i][j] = s;
    }
    __syncthreads();
    if (tid < 16) {
        float mx = -1e30f;
#pragma unroll
        for (int c = 0; c < 16; c++) mx = fmaxf(mx, X[tid][c]);
        float sm = 0.f;
#pragma unroll
        for (int c = 0; c < 16; c++) { float e = __expf(X[tid][c] - mx); X[tid][c] = e; sm += e; }
        float inv = 1.f / sm;
#pragma unroll
        for (int c = 0; c < 16; c++) X[tid][c] *= inv;
    }
    __syncthreads();
    if (tid == 0) {
        float mc = 0.f, mr = 0.f;
        for (int r = 0; r < 16; r++) {
            float s = 0.f;
            for (int c = 0; c < 16; c++) s += fabsf(X[r][c]);
            mc = fmaxf(mc, s);
        }
        for (int c = 0; c < 16; c++) {
            float s = 0.f;
            for (int r = 0; r < 16; r++) s += fabsf(X[r][c]);
            mr = fmaxf(mr, s);
        }
        float den = mc * mr;
        sden = (den == 0.f) ? 1e-8f : den;
    }
    __syncthreads();
    Z[i][j] = X[j][i] / sden;
    __syncthreads();
    for (int it = 0; it < 6; it++) {
        MM16(XZ, X, Z);
        T[i][j] = (i == j ? 7.f : 0.f) - XZ[i][j];
        __syncthreads();
        MM16(U, XZ, T);
        T[i][j] = (i == j ? 15.f : 0.f) - U[i][j];
        __syncthreads();
        MM16(U, XZ, T);
        T[i][j] = (i == j ? 13.f : 0.f) - U[i][j];
        __syncthreads();
        MM16(U, Z, T);
        Z[i][j] = 0.25f * U[i][j];
        __syncthreads();
    }
    for (int p = tid; p < L_LM * DHEAD; p += 256) {
        float s = 0.f;
#pragma unroll
        for (int pp = 0; pp < 8; pp++)
            s += g_t1p[(size_t)(bh * 8 + pp) * L_LM * DHEAD + p];
        ((float*)t1s)[p] = s;
    }
    __syncthreads();
#pragma unroll
    for (int p = 0; p < 4; p++) {
        int idx = tid + 256 * p;
        int l = idx >> 6, d = idx & 63;
        float r = 0.f;
#pragma unroll
        for (int kk = 0; kk < 16; kk++) r += Z[l][kk] * t1s[kk][d];
        g_t2[(size_t)bh * L_LM * DHEAD + idx] = r;
    }
}

// ---------------- K9: attn_out = rearrange(attn1 @ t2 + v) -> fp16 ----------
__global__ void k_attnout() {
    int bh = blockIdx.x;
    int b = bh >> 3, h = bh & 7;
    int row = blockIdx.y * 4 + (threadIdx.x >> 6);
    int d = threadIdx.x & 63;
    __shared__ float t2s[L_LM][DHEAD];
    for (int i = threadIdx.x; i < L_LM * DHEAD; i += 256)
        ((float*)t2s)[i] = g_t2[(size_t)bh * L_LM * DHEAD + i];
    __syncthreads();
    const float* a1 = &g_attn1[((size_t)bh * N_SEQ + row) * L_LM];
    float acc = g_qkv[((size_t)(b * N_SEQ + row)) * INNER3 + 2 * DIMC + h * DHEAD + d];
#pragma unroll
    for (int l = 0; l < L_LM; l++) acc += a1[l] * t2s[l][d];
    g_ao_h[((size_t)b * N_SEQ + row) * DIMC + h * DHEAD + d] = __float2half(acc);
}

// ---------------- launch ----------------
extern "C" void kernel_launch(void* const* d_in, const int* in_sizes, int n_in,
                              void* d_out, int out_size) {
    const float* x     = (const float*)d_in[0];
    const float* ln_g  = (const float*)d_in[1];
    const float* ln_b  = (const float*)d_in[2];
    const float* w_qkv = (const float*)d_in[3];
    const float* w_out = (const float*)d_in[4];
    const float* b_out = (const float*)d_in[5];
    float* out = (float*)d_out;

    cudaFuncSetAttribute(k_gemm_mma<INNER3, false>,
                         cudaFuncAttributeMaxDynamicSharedMemorySize, GEMM_SMEM);
    cudaFuncSetAttribute(k_gemm_mma<DIMC, true>,
                         cudaFuncAttributeMaxDynamicSharedMemorySize, GEMM_SMEM);

    __half *wqh, *woh, *nrm_h, *ao_h;
    cudaGetSymbolAddress((void**)&wqh, g_wqh);
    cudaGetSymbolAddress((void**)&woh, g_woh);
    cudaGetSymbolAddress((void**)&nrm_h, g_nrm_h);
    cudaGetSymbolAddress((void**)&ao_h, g_ao_h);
    float* qkv;
    cudaGetSymbolAddress((void**)&qkv, g_qkv);

    k_prep_wh<<<dim3(INNER3 / 32, DIMC / 32), dim3(32, 8)>>>(w_qkv, wqh, INNER3);
    k_prep_wh<<<dim3(DIMC / 32, DIMC / 32), dim3(32, 8)>>>(w_out, woh, DIMC);
    k_layernorm<<<ROWS / 8, dim3(32, 8)>>>(x, ln_g, ln_b);
    k_gemm_mma<INNER3, false><<<dim3(INNER3 / 128, ROWS / 256), 256, GEMM_SMEM>>>(
        nrm_h, wqh, nullptr, nullptr, qkv);
    k_landmarks<<<2048, 256>>>();
    k_sim1<<<dim3(BH, N_SEQ / 256), 256>>>();
    k_sim3<<<dim3(BH, N_SEQ / 256), 256>>>();
    k_softmax_rows<<<BH * L_LM, 256>>>();
    k_t1<<<dim3(BH, 8), 256>>>();
    k_pinv<<<BH, 256>>>();
    k_attnout<<<dim3(BH, N_SEQ / 4), 256>>>();
    k_gemm_mma<DIMC, true><<<dim3(DIMC / 128, ROWS / 256), 256, GEMM_SMEM>>>(
        ao_h, woh, x, b_out, out);
}

// round 11
// speedup vs baseline: 3.3068x; 1.0456x over previous
#include <cuda_runtime.h>
#include <cuda_fp16.h>
#include <math.h>
#include <cstdint>

// ---------------- problem constants ----------------
#define B_SZ   8
#define N_SEQ  4096
#define DIMC   512
#define HEADS  8
#define DHEAD  64
#define M_LM   256
#define L_LM   16
#define BH     64
#define ROWS   32768
#define INNER3 1536
#define SCALE_Q 0.125f
#define LN_EPS 1e-5f

// ---------------- device scratch ----------------
__device__ __half g_nrm_h[(size_t)ROWS * DIMC];       // 32 MB LN output (fp16)
__device__ __half g_qkv_h[(size_t)ROWS * INNER3];     // 96 MB qkv (fp16, q pre-scaled)
__device__ __half g_ao_h[(size_t)ROWS * DIMC];        // 32 MB attn_out (fp16)
__device__ __half g_wqh[INNER3 * DIMC];               // w_qkv^T [1536][512] fp16
__device__ __half g_woh[DIMC * DIMC];                 // w_out^T [512][512] fp16
__device__ float g_ql[BH * L_LM * DHEAD];
__device__ float g_kl[BH * L_LM * DHEAD];
__device__ float g_attn1[(size_t)BH * N_SEQ * L_LM];  // 16 MB
__device__ float g_sim3[(size_t)BH * L_LM * N_SEQ];   // 16 MB
__device__ float g_t1p[BH * 8 * L_LM * DHEAD];        // 8-way partial t1
__device__ float g_t2[BH * L_LM * DHEAD];

// ---------------- helpers ----------------
__device__ __forceinline__ uint32_t smem_u32(const void* p) {
    uint32_t a;
    asm("{ .reg .u64 t; cvta.to.shared.u64 t, %1; cvt.u32.u64 %0, t; }" : "=r"(a) : "l"(p));
    return a;
}
#define CP_ASYNC16(dst, src) \
    asm volatile("cp.async.cg.shared.global [%0], [%1], 16;" :: "r"(dst), "l"(src))
#define CP_COMMIT() asm volatile("cp.async.commit_group;" ::: "memory")
#define CP_WAIT(n)  asm volatile("cp.async.wait_group %0;" :: "n"(n) : "memory")

#define MMA_F16(c, a, b)                                                        \
    asm volatile("mma.sync.aligned.m16n8k16.row.col.f32.f16.f16.f32 "           \
        "{%0,%1,%2,%3}, {%4,%5,%6,%7}, {%8,%9}, {%0,%1,%2,%3};"                 \
        : "+f"((c)[0]), "+f"((c)[1]), "+f"((c)[2]), "+f"((c)[3])                \
        : "r"((a)[0]), "r"((a)[1]), "r"((a)[2]), "r"((a)[3]),                   \
          "r"((b)[0]), "r"((b)[1]))

// ---------------- K0: weight transpose + fp16 convert (tiled) ----------------
__global__ void k_prep_wh(const float* __restrict__ W, __half* __restrict__ Wh, int N) {
    __shared__ float t[32][33];
    int n0 = blockIdx.x * 32, k0 = blockIdx.y * 32;
    int tx = threadIdx.x, ty = threadIdx.y;
#pragma unroll
    for (int j = 0; j < 4; j++)
        t[ty + 8 * j][tx] = W[(size_t)(k0 + ty + 8 * j) * N + n0 + tx];
    __syncthreads();
#pragma unroll
    for (int j = 0; j < 4; j++)
        Wh[(size_t)(n0 + ty + 8 * j) * DIMC + k0 + tx] = __float2half(t[tx][ty + 8 * j]);
}

// ---------------- K1: LayerNorm -> fp16 ----------------
__global__ void k_layernorm(const float* __restrict__ x,
                            const float* __restrict__ gamma,
                            const float* __restrict__ beta) {
    int row = blockIdx.x * 8 + threadIdx.y;
    const float4* xr = (const float4*)(x + (size_t)row * DIMC);
    float4 v[4];
    float s = 0.f, ss = 0.f;
#pragma unroll
    for (int i = 0; i < 4; i++) {
        v[i] = xr[threadIdx.x + 32 * i];
        s  += v[i].x + v[i].y + v[i].z + v[i].w;
        ss += v[i].x * v[i].x + v[i].y * v[i].y + v[i].z * v[i].z + v[i].w * v[i].w;
    }
#pragma unroll
    for (int o = 16; o > 0; o >>= 1) {
        s  += __shfl_xor_sync(0xffffffffu, s, o);
        ss += __shfl_xor_sync(0xffffffffu, ss, o);
    }
    float mean = s * (1.f / DIMC);
    float var  = ss * (1.f / DIMC) - mean * mean;
    float rstd = rsqrtf(var + LN_EPS);
    const float4* gr = (const float4*)gamma;
    const float4* br = (const float4*)beta;
    __half2* yr = (__half2*)(g_nrm_h + (size_t)row * DIMC);
#pragma unroll
    for (int i = 0; i < 4; i++) {
        int c = threadIdx.x + 32 * i;
        float4 g4 = gr[c], b4 = br[c];
        float o0 = (v[i].x - mean) * rstd * g4.x + b4.x;
        float o1 = (v[i].y - mean) * rstd * g4.y + b4.y;
        float o2 = (v[i].z - mean) * rstd * g4.z + b4.z;
        float o3 = (v[i].w - mean) * rstd * g4.w + b4.w;
        yr[c * 2]     = __floats2half2_rn(o0, o1);
        yr[c * 2 + 1] = __floats2half2_rn(o2, o3);
    }
}

// ---------------- fp16 mma.sync GEMM ----------------
// C[ROWS][NTOT] = A[ROWS][512] @ B^T; A half [row][k], B half [n][k].
// Block tile 128x128, warp tile 64x32 (8 warps 2x4), BK=32, 3-stage cp.async, 2 CTA/SM.
#define NCHUNK 16
#define NSTAGE 3
#define T_LD 40
#define A_ST (128 * T_LD)          // halves per A stage
#define B_ST (128 * T_LD)          // halves per B stage
#define GEMM_SMEM (NSTAGE * (A_ST + B_ST) * 2)

template <int NTOT, bool IS_OUT>
__global__ __launch_bounds__(256, 2) void k_gemm_mma(
    const __half* __restrict__ A, const __half* __restrict__ Bw,
    const float* __restrict__ xres, const float* __restrict__ bias,
    void* __restrict__ Cv) {
    extern __shared__ __half smh[];
    __half* AsBase = smh;
    __half* BsBase = smh + NSTAGE * A_ST;
    const int tid = threadIdx.x;
    const int warp = tid >> 5, lane = tid & 31;
    const int wm = warp >> 2, wn = warp & 3;
    const int bm = blockIdx.y * 128, bn = blockIdx.x * 128;
    const int g = lane >> 2, q = lane & 3;

    float acc[4][4][4];
#pragma unroll
    for (int mt = 0; mt < 4; mt++)
#pragma unroll
        for (int nt = 0; nt < 4; nt++)
#pragma unroll
            for (int e = 0; e < 4; e++) acc[mt][nt][e] = 0.f;

    auto load_chunk = [&](int c) {
        int st = c % 3;
        __half* as = AsBase + st * A_ST;
        __half* bs = BsBase + st * B_ST;
        int k0 = c * 32;
#pragma unroll
        for (int t = 0; t < 2; t++) {
            int idx = tid + t * 256;           // 0..511
            int row = idx >> 2, seg = idx & 3;
            CP_ASYNC16(smem_u32(as + row * T_LD + seg * 8),
                       A + (size_t)(bm + row) * DIMC + k0 + seg * 8);
        }
#pragma unroll
        for (int t = 0; t < 2; t++) {
            int idx = tid + t * 256;
            int row = idx >> 2, seg = idx & 3;
            CP_ASYNC16(smem_u32(bs + row * T_LD + seg * 8),
                       Bw + (size_t)(bn + row) * DIMC + k0 + seg * 8);
        }
        CP_COMMIT();
    };

    load_chunk(0);
    load_chunk(1);

    for (int c = 0; c < NCHUNK; c++) {
        if (c < NCHUNK - 1) { CP_WAIT(1); } else { CP_WAIT(0); }
        __syncthreads();
        if (c + 2 < NCHUNK) load_chunk(c + 2);

        int st = c % 3;
        const __half* as = AsBase + st * A_ST + (wm * 64 + g) * T_LD + 2 * q;
        const __half* bs = BsBase + st * B_ST + (wn * 32 + g) * T_LD + 2 * q;
#pragma unroll
        for (int ks = 0; ks < 2; ks++) {
            int ko = ks * 16;
            uint32_t af[4][4], bf[4][2];
#pragma unroll
            for (int mt = 0; mt < 4; mt++) {
                const __half* p = as + mt * 16 * T_LD + ko;
                af[mt][0] = *(const uint32_t*)(p);
                af[mt][1] = *(const uint32_t*)(p + 8 * T_LD);
                af[mt][2] = *(const uint32_t*)(p + 8);
                af[mt][3] = *(const uint32_t*)(p + 8 * T_LD + 8);
            }
#pragma unroll
            for (int nt = 0; nt < 4; nt++) {
                const __half* p = bs + nt * 8 * T_LD + ko;
                bf[nt][0] = *(const uint32_t*)(p);
                bf[nt][1] = *(const uint32_t*)(p + 8);
            }
#pragma unroll
            for (int mt = 0; mt < 4; mt++)
#pragma unroll
                for (int nt = 0; nt < 4; nt++)
                    MMA_F16(acc[mt][nt], af[mt], bf[nt]);
        }
    }

    // epilogue
#pragma unroll
    for (int mt = 0; mt < 4; mt++) {
        int row0 = bm + wm * 64 + mt * 16 + g;
#pragma unroll
        for (int nt = 0; nt < 4; nt++) {
            int col = bn + wn * 32 + nt * 8 + 2 * q;
            float* c = acc[mt][nt];
            size_t o0 = (size_t)row0 * NTOT + col;
            size_t o1 = (size_t)(row0 + 8) * NTOT + col;
            if (IS_OUT) {
                float* C = (float*)Cv;
                float2 bv = *(const float2*)&bias[col];
                float2 x0 = *(const float2*)&xres[o0];
                float2 x1 = *(const float2*)&xres[o1];
                *(float2*)&C[o0] = make_float2(c[0] + x0.x + bv.x, c[1] + x0.y + bv.y);
                *(float2*)&C[o1] = make_float2(c[2] + x1.x + bv.x, c[3] + x1.y + bv.y);
            } else {
                __half* C = (__half*)Cv;
                float sc = (col < 512) ? SCALE_Q : 1.f;
                *(__half2*)&C[o0] = __floats2half2_rn(c[0] * sc, c[1] * sc);
                *(__half2*)&C[o1] = __floats2half2_rn(c[2] * sc, c[3] * sc);
            }
        }
    }
}

// ---------------- K3: landmark means (fp16 qkv) ----------------
__global__ void k_landmarks() {
    int id = blockIdx.x;
    int which = id >> 10;
    int bhl = id & 1023;
    int bh = bhl >> 4, l = bhl & 15;
    int b = bh >> 3, h = bh & 7;
    float* dst = which ? g_kl : g_ql;
    int d = threadIdx.x & 63, part = threadIdx.x >> 6;
    size_t base = ((size_t)(b * N_SEQ + l * M_LM + part * 64)) * INNER3 +
                  which * DIMC + h * DHEAD + d;
    float s = 0.f;
#pragma unroll 8
    for (int j = 0; j < 64; j++) s += __half2float(g_qkv_h[base + (size_t)j * INNER3]);
    __shared__ float red[4][64];
    red[part][d] = s;
    __syncthreads();
    if (part == 0)
        dst[(bh * L_LM + l) * DHEAD + d] =
            (red[0][d] + red[1][d] + red[2][d] + red[3][d]) * (1.f / M_LM);
}

// ---------------- K4: attn1 = softmax(q @ k_l^T) ----------------
__global__ void k_sim1() {
    int bh = blockIdx.x;
    int b = bh >> 3, h = bh & 7;
    int row = blockIdx.y * 256 + threadIdx.x;
    __shared__ float kls[L_LM][DHEAD];
    for (int i = threadIdx.x; i < L_LM * DHEAD; i += 256)
        kls[i >> 6][i & 63] = g_kl[bh * L_LM * DHEAD + i];
    __syncthreads();
    const __half2* q2 = (const __half2*)&g_qkv_h[((size_t)(b * N_SEQ + row)) * INNER3 + h * DHEAD];
    float s[L_LM];
#pragma unroll
    for (int l = 0; l < L_LM; l++) s[l] = 0.f;
#pragma unroll 8
    for (int kk = 0; kk < 32; kk++) {
        float2 qv = __half22float2(q2[kk]);
#pragma unroll
        for (int l = 0; l < L_LM; l++)
            s[l] += qv.x * kls[l][2 * kk] + qv.y * kls[l][2 * kk + 1];
    }
    float mx = s[0];
#pragma unroll
    for (int l = 1; l < L_LM; l++) mx = fmaxf(mx, s[l]);
    float sum = 0.f;
#pragma unroll
    for (int l = 0; l < L_LM; l++) { s[l] = __expf(s[l] - mx); sum += s[l]; }
    float inv = 1.f / sum;
    float* dst = &g_attn1[((size_t)bh * N_SEQ + row) * L_LM];
#pragma unroll
    for (int l = 0; l < L_LM; l += 4)
        *(float4*)&dst[l] = make_float4(s[l] * inv, s[l + 1] * inv, s[l + 2] * inv, s[l + 3] * inv);
}

// ---------------- K5: sim3 = q_l @ k^T ----------------
__global__ void k_sim3() {
    int bh = blockIdx.x;
    int b = bh >> 3, h = bh & 7;
    int j = blockIdx.y * 256 + threadIdx.x;
    __shared__ float qls[L_LM][DHEAD];
    for (int i = threadIdx.x; i < L_LM * DHEAD; i += 256)
        qls[i >> 6][i & 63] = g_ql[bh * L_LM * DHEAD + i];
    __syncthreads();
    const __half2* k2 = (const __half2*)&g_qkv_h[((size_t)(b * N_SEQ + j)) * INNER3 + DIMC + h * DHEAD];
    float s[L_LM];
#pragma unroll
    for (int l = 0; l < L_LM; l++) s[l] = 0.f;
#pragma unroll 8
    for (int kk = 0; kk < 32; kk++) {
        float2 kv = __half22float2(k2[kk]);
#pragma unroll
        for (int l = 0; l < L_LM; l++)
            s[l] += kv.x * qls[l][2 * kk] + kv.y * qls[l][2 * kk + 1];
    }
#pragma unroll
    for (int l = 0; l < L_LM; l++)
        g_sim3[((size_t)bh * L_LM + l) * N_SEQ + j] = s[l];
}

// ---------------- K6: softmax over rows of 4096 ----------------
__global__ void k_softmax_rows() {
    __shared__ float red[8];
    float* row = g_sim3 + (size_t)blockIdx.x * N_SEQ;
    int t = threadIdx.x, lane = t & 31, warp = t >> 5;
    float v[16];
    float mx = -1e30f;
#pragma unroll
    for (int i = 0; i < 16; i++) { v[i] = row[t + 256 * i]; mx = fmaxf(mx, v[i]); }
#pragma unroll
    for (int o = 16; o > 0; o >>= 1) mx = fmaxf(mx, __shfl_xor_sync(0xffffffffu, mx, o));
    if (lane == 0) red[warp] = mx;
    __syncthreads();
    mx = red[0];
#pragma unroll
    for (int w = 1; w < 8; w++) mx = fmaxf(mx, red[w]);
    __syncthreads();
    float sum = 0.f;
#pragma unroll
    for (int i = 0; i < 16; i++) { v[i] = __expf(v[i] - mx); sum += v[i]; }
#pragma unroll
    for (int o = 16; o > 0; o >>= 1) sum += __shfl_xor_sync(0xffffffffu, sum, o);
    if (lane == 0) red[warp] = sum;
    __syncthreads();
    sum = 0.f;
#pragma unroll
    for (int w = 0; w < 8; w++) sum += red[w];
    float inv = 1.f / sum;
#pragma unroll
    for (int i = 0; i < 16; i++) row[t + 256 * i] = v[i] * inv;
}

// ---------------- K7: t1 partials = attn3 @ v (8-way split) ----------------
__global__ void k_t1() {
    int bh = blockIdx.x;
    int part = blockIdx.y;
    int b = bh >> 3, h = bh & 7;
    __shared__ float a_s[L_LM][128];
    __shared__ float v_s[128][DHEAD];
    int d = threadIdx.x & 63;
    int lb = threadIdx.x >> 6;
    float acc[4] = {0.f, 0.f, 0.f, 0.f};
    for (int j0 = part * 512; j0 < part * 512 + 512; j0 += 128) {
        for (int i = threadIdx.x; i < L_LM * 128; i += 256) {
            int l = i >> 7, jj = i & 127;
            a_s[l][jj] = g_sim3[((size_t)bh * L_LM + l) * N_SEQ + j0 + jj];
        }
        for (int i = threadIdx.x; i < 128 * 8; i += 256) {
            int row = i >> 3, d8 = i & 7;
            uint4 raw = *(const uint4*)&g_qkv_h[((size_t)(b * N_SEQ + j0 + row)) * INNER3 +
                                                2 * DIMC + h * DHEAD + d8 * 8];
            const __half2* hp = (const __half2*)&raw;
#pragma unroll
            for (int e = 0; e < 4; e++) {
                float2 f = __half22float2(hp[e]);
                v_s[row][d8 * 8 + 2 * e]     = f.x;
                v_s[row][d8 * 8 + 2 * e + 1] = f.y;
            }
        }
        __syncthreads();
        for (int jj = 0; jj < 128; jj++) {
            float vv = v_s[jj][d];
#pragma unroll
            for (int p = 0; p < 4; p++) acc[p] += a_s[lb + 4 * p][jj] * vv;
        }
        __syncthreads();
    }
#pragma unroll
    for (int p = 0; p < 4; p++)
        g_t1p[((size_t)(bh * 8 + part) * L_LM + lb + 4 * p) * DHEAD + d] = acc[p];
}

// ---------------- K8: sim2 + softmax + pinv + t2 ----------------
#define MM16(Cm, Am, Bm)                                        \
    {                                                           \
        float r_ = 0.f;                                         \
        _Pragma("unroll") for (int kk_ = 0; kk_ < 16; kk_++)    \
            r_ += Am[i][kk_] * Bm[kk_][j];                      \
        __syncthreads();                                        \
        Cm[i][j] = r_;                                          \
        __syncthreads();                                        \
    }

__global__ void k_pinv() {
    int bh = blockIdx.x;
    int tid = threadIdx.x;
    int i = tid >> 4, j = tid & 15;
    __shared__ float X[16][16], Z[16][16], XZ[16][16], T[16][16], U[16][16];
    __shared__ float t1s[16][64];
    __shared__ float sden;
    {
        const float* qi = &g_ql[(bh * L_LM + i) * DHEAD];
        const float* kj = &g_kl[(bh * L_LM + j) * DHEAD];
        float s = 0.f;
#pragma unroll
        for (int kk = 0; kk < DHEAD; kk++) s += qi[kk] * kj[kk];
        X[i][j] = s;
    }
    __syncthreads();
    if (tid < 16) {
        float mx = -1e30f;
#pragma unroll
        for (int c = 0; c < 16; c++) mx = fmaxf(mx, X[tid][c]);
        float sm = 0.f;
#pragma unroll
        for (int c = 0; c < 16; c++) { float e = __expf(X[tid][c] - mx); X[tid][c] = e; sm += e; }
        float inv = 1.f / sm;
#pragma unroll
        for (int c = 0; c < 16; c++) X[tid][c] *= inv;
    }
    __syncthreads();
    if (tid == 0) {
        float mc = 0.f, mr = 0.f;
        for (int r = 0; r < 16; r++) {
            float s = 0.f;
            for (int c = 0; c < 16; c++) s += fabsf(X[r][c]);
            mc = fmaxf(mc, s);
        }
        for (int c = 0; c < 16; c++) {
            float s = 0.f;
            for (int r = 0; r < 16; r++) s += fabsf(X[r][c]);
            mr = fmaxf(mr, s);
        }
        float den = mc * mr;
        sden = (den == 0.f) ? 1e-8f : den;
    }
    __syncthreads();
    Z[i][j] = X[j][i] / sden;
    __syncthreads();
    for (int it = 0; it < 6; it++) {
        MM16(XZ, X, Z);
        T[i][j] = (i == j ? 7.f : 0.f) - XZ[i][j];
        __syncthreads();
        MM16(U, XZ, T);
        T[i][j] = (i == j ? 15.f : 0.f) - U[i][j];
        __syncthreads();
        MM16(U, XZ, T);
        T[i][j] = (i == j ? 13.f : 0.f) - U[i][j];
        __syncthreads();
        MM16(U, Z, T);
        Z[i][j] = 0.25f * U[i][j];
        __syncthreads();
    }
    for (int p = tid; p < L_LM * DHEAD; p += 256) {
        float s = 0.f;
#pragma unroll
        for (int pp = 0; pp < 8; pp++)
            s += g_t1p[(size_t)(bh * 8 + pp) * L_LM * DHEAD + p];
        ((float*)t1s)[p] = s;
    }
    __syncthreads();
#pragma unroll
    for (int p = 0; p < 4; p++) {
        int idx = tid + 256 * p;
        int l = idx >> 6, d = idx & 63;
        float r = 0.f;
#pragma unroll
        for (int kk = 0; kk < 16; kk++) r += Z[l][kk] * t1s[kk][d];
        g_t2[(size_t)bh * L_LM * DHEAD + idx] = r;
    }
}

// ---------------- K9: attn_out = rearrange(attn1 @ t2 + v) -> fp16 ----------
__global__ void k_attnout() {
    int bh = blockIdx.x;
    int b = bh >> 3, h = bh & 7;
    int row = blockIdx.y * 4 + (threadIdx.x >> 6);
    int d = threadIdx.x & 63;
    __shared__ float t2s[L_LM][DHEAD];
    for (int i = threadIdx.x; i < L_LM * DHEAD; i += 256)
        ((float*)t2s)[i] = g_t2[(size_t)bh * L_LM * DHEAD + i];
    __syncthreads();
    const float* a1 = &g_attn1[((size_t)bh * N_SEQ + row) * L_LM];
    float acc = __half2float(g_qkv_h[((size_t)(b * N_SEQ + row)) * INNER3 +
                                     2 * DIMC + h * DHEAD + d]);
#pragma unroll
    for (int l = 0; l < L_LM; l++) acc += a1[l] * t2s[l][d];
    g_ao_h[((size_t)b * N_SEQ + row) * DIMC + h * DHEAD + d] = __float2half(acc);
}

// ---------------- launch ----------------
extern "C" void kernel_launch(void* const* d_in, const int* in_sizes, int n_in,
                              void* d_out, int out_size) {
    const float* x     = (const float*)d_in[0];
    const float* ln_g  = (const float*)d_in[1];
    const float* ln_b  = (const float*)d_in[2];
    const float* w_qkv = (const float*)d_in[3];
    const float* w_out = (const float*)d_in[4];
    const float* b_out = (const float*)d_in[5];
    float* out = (float*)d_out;

    cudaFuncSetAttribute(k_gemm_mma<INNER3, false>,
                         cudaFuncAttributeMaxDynamicSharedMemorySize, GEMM_SMEM);
    cudaFuncSetAttribute(k_gemm_mma<DIMC, true>,
                         cudaFuncAttributeMaxDynamicSharedMemorySize, GEMM_SMEM);

    __half *wqh, *woh, *nrm_h, *ao_h, *qkv_h;
    cudaGetSymbolAddress((void**)&wqh, g_wqh);
    cudaGetSymbolAddress((void**)&woh, g_woh);
    cudaGetSymbolAddress((void**)&nrm_h, g_nrm_h);
    cudaGetSymbolAddress((void**)&ao_h, g_ao_h);
    cudaGetSymbolAddress((void**)&qkv_h, g_qkv_h);

    k_prep_wh<<<dim3(INNER3 / 32, DIMC / 32), dim3(32, 8)>>>(w_qkv, wqh, INNER3);
    k_prep_wh<<<dim3(DIMC / 32, DIMC / 32), dim3(32, 8)>>>(w_out, woh, DIMC);
    k_layernorm<<<ROWS / 8, dim3(32, 8)>>>(x, ln_g, ln_b);
    k_gemm_mma<INNER3, false><<<dim3(INNER3 / 128, ROWS / 128), 256, GEMM_SMEM>>>(
        nrm_h, wqh, nullptr, nullptr, qkv_h);
    k_landmarks<<<2048, 256>>>();
    k_sim1<<<dim3(BH, N_SEQ / 256), 256>>>();
    k_sim3<<<dim3(BH, N_SEQ / 256), 256>>>();
    k_softmax_rows<<<BH * L_LM, 256>>>();
    k_t1<<<dim3(BH, 8), 256>>>();
    k_pinv<<<BH, 256>>>();
    k_attnout<<<dim3(BH, N_SEQ / 4), 256>>>();
    k_gemm_mma<DIMC, true><<<dim3(DIMC / 128, ROWS / 128), 256, GEMM_SMEM>>>(
        ao_h, woh, x, b_out, out);
}

// round 12
// speedup vs baseline: 3.5257x; 1.0662x over previous
#include <cuda_runtime.h>
#include <cuda_fp16.h>
#include <math.h>
#include <cstdint>

// ---------------- problem constants ----------------
#define B_SZ   8
#define N_SEQ  4096
#define DIMC   512
#define HEADS  8
#define DHEAD  64
#define M_LM   256
#define L_LM   16
#define BH     64
#define ROWS   32768
#define INNER3 1536
#define SCALE_Q 0.125f
#define LN_EPS 1e-5f

// ---------------- device scratch ----------------
__device__ __half g_nrm_h[(size_t)ROWS * DIMC];       // 32 MB LN output (fp16)
__device__ __half g_qkv_h[(size_t)ROWS * INNER3];     // 96 MB qkv (fp16, q pre-scaled)
__device__ __half g_ao_h[(size_t)ROWS * DIMC];        // 32 MB attn_out (fp16)
__device__ __half g_wqh[INNER3 * DIMC];               // w_qkv^T [1536][512] fp16
__device__ __half g_woh[DIMC * DIMC];                 // w_out^T [512][512] fp16
__device__ float g_ql[BH * L_LM * DHEAD];
__device__ float g_kl[BH * L_LM * DHEAD];
__device__ float g_attn1[(size_t)BH * N_SEQ * L_LM];  // 16 MB
__device__ float g_sim3[(size_t)BH * L_LM * N_SEQ];   // 16 MB
__device__ float g_t1p[BH * 8 * L_LM * DHEAD];        // 8-way partial t1
__device__ float g_t2[BH * L_LM * DHEAD];

// ---------------- helpers ----------------
__device__ __forceinline__ uint32_t smem_u32(const void* p) {
    uint32_t a;
    asm("{ .reg .u64 t; cvta.to.shared.u64 t, %1; cvt.u32.u64 %0, t; }" : "=r"(a) : "l"(p));
    return a;
}
#define CP_ASYNC16(dst, src) \
    asm volatile("cp.async.cg.shared.global [%0], [%1], 16;" :: "r"(dst), "l"(src))
#define CP_COMMIT() asm volatile("cp.async.commit_group;" ::: "memory")
#define CP_WAIT(n)  asm volatile("cp.async.wait_group %0;" :: "n"(n) : "memory")

#define MMA_F16(c, a, b)                                                        \
    asm volatile("mma.sync.aligned.m16n8k16.row.col.f32.f16.f16.f32 "           \
        "{%0,%1,%2,%3}, {%4,%5,%6,%7}, {%8,%9}, {%0,%1,%2,%3};"                 \
        : "+f"((c)[0]), "+f"((c)[1]), "+f"((c)[2]), "+f"((c)[3])                \
        : "r"((a)[0]), "r"((a)[1]), "r"((a)[2]), "r"((a)[3]),                   \
          "r"((b)[0]), "r"((b)[1]))

#define LDSM_X4(r0, r1, r2, r3, addr)                                           \
    asm volatile("ldmatrix.sync.aligned.m8n8.x4.shared.b16 {%0,%1,%2,%3}, [%4];"\
        : "=r"(r0), "=r"(r1), "=r"(r2), "=r"(r3) : "r"(addr))

// ---------------- K0: weight transpose + fp16 convert (tiled) ----------------
__global__ void k_prep_wh(const float* __restrict__ W, __half* __restrict__ Wh, int N) {
    __shared__ float t[32][33];
    int n0 = blockIdx.x * 32, k0 = blockIdx.y * 32;
    int tx = threadIdx.x, ty = threadIdx.y;
#pragma unroll
    for (int j = 0; j < 4; j++)
        t[ty + 8 * j][tx] = W[(size_t)(k0 + ty + 8 * j) * N + n0 + tx];
    __syncthreads();
#pragma unroll
    for (int j = 0; j < 4; j++)
        Wh[(size_t)(n0 + ty + 8 * j) * DIMC + k0 + tx] = __float2half(t[tx][ty + 8 * j]);
}

// ---------------- K1: LayerNorm -> fp16 ----------------
__global__ void k_layernorm(const float* __restrict__ x,
                            const float* __restrict__ gamma,
                            const float* __restrict__ beta) {
    int row = blockIdx.x * 8 + threadIdx.y;
    const float4* xr = (const float4*)(x + (size_t)row * DIMC);
    float4 v[4];
    float s = 0.f, ss = 0.f;
#pragma unroll
    for (int i = 0; i < 4; i++) {
        v[i] = xr[threadIdx.x + 32 * i];
        s  += v[i].x + v[i].y + v[i].z + v[i].w;
        ss += v[i].x * v[i].x + v[i].y * v[i].y + v[i].z * v[i].z + v[i].w * v[i].w;
    }
#pragma unroll
    for (int o = 16; o > 0; o >>= 1) {
        s  += __shfl_xor_sync(0xffffffffu, s, o);
        ss += __shfl_xor_sync(0xffffffffu, ss, o);
    }
    float mean = s * (1.f / DIMC);
    float var  = ss * (1.f / DIMC) - mean * mean;
    float rstd = rsqrtf(var + LN_EPS);
    const float4* gr = (const float4*)gamma;
    const float4* br = (const float4*)beta;
    __half2* yr = (__half2*)(g_nrm_h + (size_t)row * DIMC);
#pragma unroll
    for (int i = 0; i < 4; i++) {
        int c = threadIdx.x + 32 * i;
        float4 g4 = gr[c], b4 = br[c];
        float o0 = (v[i].x - mean) * rstd * g4.x + b4.x;
        float o1 = (v[i].y - mean) * rstd * g4.y + b4.y;
        float o2 = (v[i].z - mean) * rstd * g4.z + b4.z;
        float o3 = (v[i].w - mean) * rstd * g4.w + b4.w;
        yr[c * 2]     = __floats2half2_rn(o0, o1);
        yr[c * 2 + 1] = __floats2half2_rn(o2, o3);
    }
}

// ---------------- fp16 mma.sync GEMM (ldmatrix fragments) ----------------
// C[ROWS][NTOT] = A[ROWS][512] @ B^T; A half [row][k], B half [n][k].
// Block tile 128x128, warp tile 64x32 (8 warps 2x4), BK=32, 3-stage cp.async, 2 CTA/SM.
#define NCHUNK 16
#define NSTAGE 3
#define T_LD 40
#define A_ST (128 * T_LD)          // halves per A stage
#define B_ST (128 * T_LD)          // halves per B stage
#define GEMM_SMEM (NSTAGE * (A_ST + B_ST) * 2)

template <int NTOT, bool IS_OUT>
__global__ __launch_bounds__(256, 2) void k_gemm_mma(
    const __half* __restrict__ A, const __half* __restrict__ Bw,
    const float* __restrict__ xres, const float* __restrict__ bias,
    void* __restrict__ Cv) {
    extern __shared__ __half smh[];
    __half* AsBase = smh;
    __half* BsBase = smh + NSTAGE * A_ST;
    const int tid = threadIdx.x;
    const int warp = tid >> 5, lane = tid & 31;
    const int wm = warp >> 2, wn = warp & 3;
    const int bm = blockIdx.y * 128, bn = blockIdx.x * 128;
    const int g = lane >> 2, q = lane & 3;
    const int lr = lane & 7, sel = lane >> 3;    // ldmatrix lane decomposition

    // per-lane ldmatrix offsets (in halves)
    const uint32_t a_lane = (uint32_t)(((sel & 1) * 8 + lr) * T_LD + (sel >> 1) * 8);
    const uint32_t b_lane = (uint32_t)(((sel >> 1) * 8 + lr) * T_LD + (sel & 1) * 8);

    float acc[4][4][4];
#pragma unroll
    for (int mt = 0; mt < 4; mt++)
#pragma unroll
        for (int nt = 0; nt < 4; nt++)
#pragma unroll
            for (int e = 0; e < 4; e++) acc[mt][nt][e] = 0.f;

    auto load_chunk = [&](int c) {
        int st = c % 3;
        __half* as = AsBase + st * A_ST;
        __half* bs = BsBase + st * B_ST;
        int k0 = c * 32;
#pragma unroll
        for (int t = 0; t < 2; t++) {
            int idx = tid + t * 256;           // 0..511
            int row = idx >> 2, seg = idx & 3;
            CP_ASYNC16(smem_u32(as + row * T_LD + seg * 8),
                       A + (size_t)(bm + row) * DIMC + k0 + seg * 8);
        }
#pragma unroll
        for (int t = 0; t < 2; t++) {
            int idx = tid + t * 256;
            int row = idx >> 2, seg = idx & 3;
            CP_ASYNC16(smem_u32(bs + row * T_LD + seg * 8),
                       Bw + (size_t)(bn + row) * DIMC + k0 + seg * 8);
        }
        CP_COMMIT();
    };

    load_chunk(0);
    load_chunk(1);

    const uint32_t asb0 = smem_u32(AsBase);
    const uint32_t bsb0 = smem_u32(BsBase);

    for (int c = 0; c < NCHUNK; c++) {
        if (c < NCHUNK - 1) { CP_WAIT(1); } else { CP_WAIT(0); }
        __syncthreads();
        if (c + 2 < NCHUNK) load_chunk(c + 2);

        int st = c % 3;
        // base addresses (bytes) for this warp's tiles in this stage
        uint32_t a_base = asb0 + 2u * ((uint32_t)st * A_ST + (uint32_t)(wm * 64) * T_LD + a_lane);
        uint32_t b_base = bsb0 + 2u * ((uint32_t)st * B_ST + (uint32_t)(wn * 32) * T_LD + b_lane);
#pragma unroll
        for (int ks = 0; ks < 2; ks++) {
            int ko = ks * 16;
            uint32_t af[4][4], bf[4][2];
#pragma unroll
            for (int mt = 0; mt < 4; mt++)
                LDSM_X4(af[mt][0], af[mt][1], af[mt][2], af[mt][3],
                        a_base + 2u * (uint32_t)(mt * 16 * T_LD + ko));
#pragma unroll
            for (int p = 0; p < 2; p++)
                LDSM_X4(bf[2 * p][0], bf[2 * p][1], bf[2 * p + 1][0], bf[2 * p + 1][1],
                        b_base + 2u * (uint32_t)(p * 16 * T_LD + ko));
#pragma unroll
            for (int mt = 0; mt < 4; mt++)
#pragma unroll
                for (int nt = 0; nt < 4; nt++)
                    MMA_F16(acc[mt][nt], af[mt], bf[nt]);
        }
    }

    // epilogue
#pragma unroll
    for (int mt = 0; mt < 4; mt++) {
        int row0 = bm + wm * 64 + mt * 16 + g;
#pragma unroll
        for (int nt = 0; nt < 4; nt++) {
            int col = bn + wn * 32 + nt * 8 + 2 * q;
            float* c = acc[mt][nt];
            size_t o0 = (size_t)row0 * NTOT + col;
            size_t o1 = (size_t)(row0 + 8) * NTOT + col;
            if (IS_OUT) {
                float* C = (float*)Cv;
                float2 bv = *(const float2*)&bias[col];
                float2 x0 = *(const float2*)&xres[o0];
                float2 x1 = *(const float2*)&xres[o1];
                *(float2*)&C[o0] = make_float2(c[0] + x0.x + bv.x, c[1] + x0.y + bv.y);
                *(float2*)&C[o1] = make_float2(c[2] + x1.x + bv.x, c[3] + x1.y + bv.y);
            } else {
                __half* C = (__half*)Cv;
                float sc = (col < 512) ? SCALE_Q : 1.f;
                *(__half2*)&C[o0] = __floats2half2_rn(c[0] * sc, c[1] * sc);
                *(__half2*)&C[o1] = __floats2half2_rn(c[2] * sc, c[3] * sc);
            }
        }
    }
}

// ---------------- K3: landmark means (fp16 qkv, half2 loads) ----------------
__global__ void k_landmarks() {
    int id = blockIdx.x;
    int which = id >> 10;
    int bhl = id & 1023;
    int bh = bhl >> 4, l = bhl & 15;
    int b = bh >> 3, h = bh & 7;
    float* dst = which ? g_kl : g_ql;
    int d2 = threadIdx.x & 31, part = threadIdx.x >> 5;   // 32 half2 cols, 8 parts
    const __half2* base = (const __half2*)&g_qkv_h[
        ((size_t)(b * N_SEQ + l * M_LM + part * 32)) * INNER3 +
        which * DIMC + h * DHEAD] + d2;
    float2 s = make_float2(0.f, 0.f);
#pragma unroll 8
    for (int j = 0; j < 32; j++) {
        float2 f = __half22float2(base[(size_t)j * (INNER3 / 2)]);
        s.x += f.x; s.y += f.y;
    }
    __shared__ float2 red[8][32];
    red[part][d2] = s;
    __syncthreads();
    if (part == 0) {
        float2 t = red[0][d2];
#pragma unroll
        for (int p = 1; p < 8; p++) {
            t.x += red[p][d2].x;
            t.y += red[p][d2].y;
        }
        float* o = &dst[(bh * L_LM + l) * DHEAD + d2 * 2];
        o[0] = t.x * (1.f / M_LM);
        o[1] = t.y * (1.f / M_LM);
    }
}

// ---------------- K4: attn1 = softmax(q @ k_l^T) ----------------
__global__ void k_sim1() {
    int bh = blockIdx.x;
    int b = bh >> 3, h = bh & 7;
    int row = blockIdx.y * 256 + threadIdx.x;
    __shared__ float kls[L_LM][DHEAD];
    for (int i = threadIdx.x; i < L_LM * DHEAD; i += 256)
        kls[i >> 6][i & 63] = g_kl[bh * L_LM * DHEAD + i];
    __syncthreads();
    const __half2* q2 = (const __half2*)&g_qkv_h[((size_t)(b * N_SEQ + row)) * INNER3 + h * DHEAD];
    float s[L_LM];
#pragma unroll
    for (int l = 0; l < L_LM; l++) s[l] = 0.f;
#pragma unroll 8
    for (int kk = 0; kk < 32; kk++) {
        float2 qv = __half22float2(q2[kk]);
#pragma unroll
        for (int l = 0; l < L_LM; l++)
            s[l] += qv.x * kls[l][2 * kk] + qv.y * kls[l][2 * kk + 1];
    }
    float mx = s[0];
#pragma unroll
    for (int l = 1; l < L_LM; l++) mx = fmaxf(mx, s[l]);
    float sum = 0.f;
#pragma unroll
    for (int l = 0; l < L_LM; l++) { s[l] = __expf(s[l] - mx); sum += s[l]; }
    float inv = 1.f / sum;
    float* dst = &g_attn1[((size_t)bh * N_SEQ + row) * L_LM];
#pragma unroll
    for (int l = 0; l < L_LM; l += 4)
        *(float4*)&dst[l] = make_float4(s[l] * inv, s[l + 1] * inv, s[l + 2] * inv, s[l + 3] * inv);
}

// ---------------- K5: sim3 = q_l @ k^T ----------------
__global__ void k_sim3() {
    int bh = blockIdx.x;
    int b = bh >> 3, h = bh & 7;
    int j = blockIdx.y * 256 + threadIdx.x;
    __shared__ float qls[L_LM][DHEAD];
    for (int i = threadIdx.x; i < L_LM * DHEAD; i += 256)
        qls[i >> 6][i & 63] = g_ql[bh * L_LM * DHEAD + i];
    __syncthreads();
    const __half2* k2 = (const __half2*)&g_qkv_h[((size_t)(b * N_SEQ + j)) * INNER3 + DIMC + h * DHEAD];
    float s[L_LM];
#pragma unroll
    for (int l = 0; l < L_LM; l++) s[l] = 0.f;
#pragma unroll 8
    for (int kk = 0; kk < 32; kk++) {
        float2 kv = __half22float2(k2[kk]);
#pragma unroll
        for (int l = 0; l < L_LM; l++)
            s[l] += kv.x * qls[l][2 * kk] + kv.y * qls[l][2 * kk + 1];
    }
#pragma unroll
    for (int l = 0; l < L_LM; l++)
        g_sim3[((size_t)bh * L_LM + l) * N_SEQ + j] = s[l];
}

// ---------------- K6: softmax over rows of 4096 ----------------
__global__ void k_softmax_rows() {
    __shared__ float red[8];
    float* row = g_sim3 + (size_t)blockIdx.x * N_SEQ;
    int t = threadIdx.x, lane = t & 31, warp = t >> 5;
    float v[16];
    float mx = -1e30f;
#pragma unroll
    for (int i = 0; i < 16; i++) { v[i] = row[t + 256 * i]; mx = fmaxf(mx, v[i]); }
#pragma unroll
    for (int o = 16; o > 0; o >>= 1) mx = fmaxf(mx, __shfl_xor_sync(0xffffffffu, mx, o));
    if (lane == 0) red[warp] = mx;
    __syncthreads();
    mx = red[0];
#pragma unroll
    for (int w = 1; w < 8; w++) mx = fmaxf(mx, red[w]);
    __syncthreads();
    float sum = 0.f;
#pragma unroll
    for (int i = 0; i < 16; i++) { v[i] = __expf(v[i] - mx); sum += v[i]; }
#pragma unroll
    for (int o = 16; o > 0; o >>= 1) sum += __shfl_xor_sync(0xffffffffu, sum, o);
    if (lane == 0) red[warp] = sum;
    __syncthreads();
    sum = 0.f;
#pragma unroll
    for (int w = 0; w < 8; w++) sum += red[w];
    float inv = 1.f / sum;
#pragma unroll
    for (int i = 0; i < 16; i++) row[t + 256 * i] = v[i] * inv;
}

// ---------------- K7: t1 partials = attn3 @ v (8-way split) ----------------
__global__ void k_t1() {
    int bh = blockIdx.x;
    int part = blockIdx.y;
    int b = bh >> 3, h = bh & 7;
    __shared__ float a_s[L_LM][128];
    __shared__ float v_s[128][DHEAD];
    int d = threadIdx.x & 63;
    int lb = threadIdx.x >> 6;
    float acc[4] = {0.f, 0.f, 0.f, 0.f};
    for (int j0 = part * 512; j0 < part * 512 + 512; j0 += 128) {
        for (int i = threadIdx.x; i < L_LM * 128; i += 256) {
            int l = i >> 7, jj = i & 127;
            a_s[l][jj] = g_sim3[((size_t)bh * L_LM + l) * N_SEQ + j0 + jj];
        }
        for (int i = threadIdx.x; i < 128 * 8; i += 256) {
            int row = i >> 3, d8 = i & 7;
            uint4 raw = *(const uint4*)&g_qkv_h[((size_t)(b * N_SEQ + j0 + row)) * INNER3 +
                                                2 * DIMC + h * DHEAD + d8 * 8];
            const __half2* hp = (const __half2*)&raw;
#pragma unroll
            for (int e = 0; e < 4; e++) {
                float2 f = __half22float2(hp[e]);
                v_s[row][d8 * 8 + 2 * e]     = f.x;
                v_s[row][d8 * 8 + 2 * e + 1] = f.y;
            }
        }
        __syncthreads();
        for (int jj = 0; jj < 128; jj++) {
            float vv = v_s[jj][d];
#pragma unroll
            for (int p = 0; p < 4; p++) acc[p] += a_s[lb + 4 * p][jj] * vv;
        }
        __syncthreads();
    }
#pragma unroll
    for (int p = 0; p < 4; p++)
        g_t1p[((size_t)(bh * 8 + part) * L_LM + lb + 4 * p) * DHEAD + d] = acc[p];
}

// ---------------- K8: sim2 + softmax + pinv + t2 ----------------
#define MM16(Cm, Am, Bm)                                        \
    {                                                           \
        float r_ = 0.f;                                         \
        _Pragma("unroll") for (int kk_ = 0; kk_ < 16; kk_++)    \
            r_ += Am[i][kk_] * Bm[kk_][j];                      \
        __syncthreads();                                        \
        Cm[i][j] = r_;                                          \
        __syncthreads();                                        \
    }

__global__ void k_pinv() {
    int bh = blockIdx.x;
    int tid = threadIdx.x;
    int i = tid >> 4, j = tid & 15;
    __shared__ float X[16][16], Z[16][16], XZ[16][16], T[16][16], U[16][16];
    __shared__ float t1s[16][64];
    __shared__ float sden;
    {
        const float* qi = &g_ql[(bh * L_LM + i) * DHEAD];
        const float* kj = &g_kl[(bh * L_LM + j) * DHEAD];
        float s = 0.f;
#pragma unroll
        for (int kk = 0; kk < DHEAD; kk++) s += qi[kk] * kj[kk];
        X[i][j] = s;
    }
    __syncthreads();
    if (tid < 16) {
        float mx = -1e30f;
#pragma unroll
        for (int c = 0; c < 16; c++) mx = fmaxf(mx, X[tid][c]);
        float sm = 0.f;
#pragma unroll
        for (int c = 0; c < 16; c++) { float e = __expf(X[tid][c] - mx); X[tid][c] = e; sm += e; }
        float inv = 1.f / sm;
#pragma unroll
        for (int c = 0; c < 16; c++) X[tid][c] *= inv;
    }
    __syncthreads();
    if (tid == 0) {
        float mc = 0.f, mr = 0.f;
        for (int r = 0; r < 16; r++) {
            float s = 0.f;
            for (int c = 0; c < 16; c++) s += fabsf(X[r][c]);
            mc = fmaxf(mc, s);
        }
        for (int c = 0; c < 16; c++) {
            float s = 0.f;
            for (int r = 0; r < 16; r++) s += fabsf(X[r][c]);
            mr = fmaxf(mr, s);
        }
        float den = mc * mr;
        sden = (den == 0.f) ? 1e-8f : den;
    }
    __syncthreads();
    Z[i][j] = X[j][i] / sden;
    __syncthreads();
    for (int it = 0; it < 6; it++) {
        MM16(XZ, X, Z);
        T[i][j] = (i == j ? 7.f : 0.f) - XZ[i][j];
        __syncthreads();
        MM16(U, XZ, T);
        T[i][j] = (i == j ? 15.f : 0.f) - U[i][j];
        __syncthreads();
        MM16(U, XZ, T);
        T[i][j] = (i == j ? 13.f : 0.f) - U[i][j];
        __syncthreads();
        MM16(U, Z, T);
        Z[i][j] = 0.25f * U[i][j];
        __syncthreads();
    }
    for (int p = tid; p < L_LM * DHEAD; p += 256) {
        float s = 0.f;
#pragma unroll
        for (int pp = 0; pp < 8; pp++)
            s += g_t1p[(size_t)(bh * 8 + pp) * L_LM * DHEAD + p];
        ((float*)t1s)[p] = s;
    }
    __syncthreads();
#pragma unroll
    for (int p = 0; p < 4; p++) {
        int idx = tid + 256 * p;
        int l = idx >> 6, d = idx & 63;
        float r = 0.f;
#pragma unroll
        for (int kk = 0; kk < 16; kk++) r += Z[l][kk] * t1s[kk][d];
        g_t2[(size_t)bh * L_LM * DHEAD + idx] = r;
    }
}

// ---------------- K9: attn_out = rearrange(attn1 @ t2 + v) -> fp16 ----------
__global__ void k_attnout() {
    int bh = blockIdx.x;
    int b = bh >> 3, h = bh & 7;
    int row = blockIdx.y * 4 + (threadIdx.x >> 6);
    int d = threadIdx.x & 63;
    __shared__ float t2s[L_LM][DHEAD];
    for (int i = threadIdx.x; i < L_LM * DHEAD; i += 256)
        ((float*)t2s)[i] = g_t2[(size_t)bh * L_LM * DHEAD + i];
    __syncthreads();
    const float* a1 = &g_attn1[((size_t)bh * N_SEQ + row) * L_LM];
    float acc = __half2float(g_qkv_h[((size_t)(b * N_SEQ + row)) * INNER3 +
                                     2 * DIMC + h * DHEAD + d]);
#pragma unroll
    for (int l = 0; l < L_LM; l++) acc += a1[l] * t2s[l][d];
    g_ao_h[((size_t)b * N_SEQ + row) * DIMC + h * DHEAD + d] = __float2half(acc);
}

// ---------------- launch ----------------
extern "C" void kernel_launch(void* const* d_in, const int* in_sizes, int n_in,
                              void* d_out, int out_size) {
    const float* x     = (const float*)d_in[0];
    const float* ln_g  = (const float*)d_in[1];
    const float* ln_b  = (const float*)d_in[2];
    const float* w_qkv = (const float*)d_in[3];
    const float* w_out = (const float*)d_in[4];
    const float* b_out = (const float*)d_in[5];
    float* out = (float*)d_out;

    cudaFuncSetAttribute(k_gemm_mma<INNER3, false>,
                         cudaFuncAttributeMaxDynamicSharedMemorySize, GEMM_SMEM);
    cudaFuncSetAttribute(k_gemm_mma<DIMC, true>,
                         cudaFuncAttributeMaxDynamicSharedMemorySize, GEMM_SMEM);

    __half *wqh, *woh, *nrm_h, *ao_h, *qkv_h;
    cudaGetSymbolAddress((void**)&wqh, g_wqh);
    cudaGetSymbolAddress((void**)&woh, g_woh);
    cudaGetSymbolAddress((void**)&nrm_h, g_nrm_h);
    cudaGetSymbolAddress((void**)&ao_h, g_ao_h);
    cudaGetSymbolAddress((void**)&qkv_h, g_qkv_h);

    k_prep_wh<<<dim3(INNER3 / 32, DIMC / 32), dim3(32, 8)>>>(w_qkv, wqh, INNER3);
    k_prep_wh<<<dim3(DIMC / 32, DIMC / 32), dim3(32, 8)>>>(w_out, woh, DIMC);
    k_layernorm<<<ROWS / 8, dim3(32, 8)>>>(x, ln_g, ln_b);
    k_gemm_mma<INNER3, false><<<dim3(INNER3 / 128, ROWS / 128), 256, GEMM_SMEM>>>(
        nrm_h, wqh, nullptr, nullptr, qkv_h);
    k_landmarks<<<2048, 256>>>();
    k_sim1<<<dim3(BH, N_SEQ / 256), 256>>>();
    k_sim3<<<dim3(BH, N_SEQ / 256), 256>>>();
    k_softmax_rows<<<BH * L_LM, 256>>>();
    k_t1<<<dim3(BH, 8), 256>>>();
    k_pinv<<<BH, 256>>>();
    k_attnout<<<dim3(BH, N_SEQ / 4), 256>>>();
    k_gemm_mma<DIMC, true><<<dim3(DIMC / 128, ROWS / 128), 256, GEMM_SMEM>>>(
        ao_h, woh, x, b_out, out);
}